// round 8
// baseline (speedup 1.0000x reference)
#include <cuda_runtime.h>
#include <cstdint>

#define BATCH  2
#define SEQ    2048
#define DIM    2048
#define NH     32
#define NKV    8
#define HD     64
#define KVDIM  (NKV*HD)     // 512
#define REP    (NH/NKV)     // 4
#define HALFD  (HD/2)       // 32

// ---------------- scratch (device globals; no allocations allowed) ----------
__device__ __align__(16) float g_q[(size_t)BATCH*SEQ*NH*HD];    // 32 MB
__device__ __align__(16) float g_k[(size_t)BATCH*SEQ*NKV*HD];   // 8 MB
__device__ __align__(16) float g_v[(size_t)BATCH*SEQ*NKV*HD];   // 8 MB
__device__ __align__(16) float g_o[(size_t)BATCH*SEQ*NH*HD];    // 32 MB
__device__ __align__(16) float g_xt[(size_t)BATCH*SEQ*DIM];     // 32 MB (tf32 x)
__device__ __align__(16) float g_wt[(size_t)10485760];          // 42 MB (tf32 weights)

#define WQ_OFF 0
#define WK_OFF 4194304
#define WV_OFF 5242880
#define WO_OFF 6291456

__device__ __forceinline__ uint32_t tf32u(float x) {
    uint32_t r;
    asm("cvt.rna.tf32.f32 %0, %1;" : "=r"(r) : "f"(x));
    return r;
}
__device__ __forceinline__ float tf32f(float x) {
    return __uint_as_float(tf32u(x));
}

__device__ __forceinline__ uint32_t smem_u32(const void* p) {
    uint32_t a;
    asm("{ .reg .u64 t; cvta.to.shared.u64 t, %1; cvt.u32.u64 %0, t; }"
        : "=r"(a) : "l"(p));
    return a;
}

#define CP_ASYNC16(dst, src) \
    asm volatile("cp.async.cg.shared.global [%0], [%1], 16;" \
        :: "r"(dst), "l"(src))
#define CP_COMMIT() asm volatile("cp.async.commit_group;")
#define CP_WAIT(N)  asm volatile("cp.async.wait_group %0;" :: "n"(N))

// m16n8k8 tf32 mma: D = A(16x8) * B(8x8) + D, A row-major, B K-major
__device__ __forceinline__ void mma_tf32(float c[4], const uint32_t a[4],
                                         const uint32_t b[2]) {
    asm volatile(
        "mma.sync.aligned.m16n8k8.row.col.f32.tf32.tf32.f32 "
        "{%0,%1,%2,%3}, {%4,%5,%6,%7}, {%8,%9}, {%0,%1,%2,%3};"
        : "+f"(c[0]), "+f"(c[1]), "+f"(c[2]), "+f"(c[3])
        : "r"(a[0]), "r"(a[1]), "r"(a[2]), "r"(a[3]),
          "r"(b[0]), "r"(b[1]));
}

// ---------------------------------------------------------------------------
// tf32 rounding pre-pass (in == out allowed; idempotent)
// ---------------------------------------------------------------------------
__global__ void tf32_round_kernel(const float* __restrict__ in,
                                  float* __restrict__ out, int n4)
{
    int i = blockIdx.x * blockDim.x + threadIdx.x;
    if (i >= n4) return;
    float4 v = *(const float4*)(in + 4 * (size_t)i);
    v.x = tf32f(v.x); v.y = tf32f(v.y);
    v.z = tf32f(v.z); v.w = tf32f(v.w);
    *(float4*)(out + 4 * (size_t)i) = v;
}

// ===========================================================================
// Tensor-core GEMM (tf32 mma.sync): C[M,N] = A[M,K] * W[N,K]^T, row-major.
// Inputs must be pre-rounded to tf32. 128x128 tile, BK=32, 3-stage cp.async
// pipeline, 256 threads. Smem: 3 stages x (A 128x36 + W 128x36) = 110592 B.
// ===========================================================================
#define GBM 128
#define GBN 128
#define GBK 32
#define LDSS 36
#define TILE_FLOATS (GBM * LDSS)                 // 4608
#define STAGE_FLOATS (2 * TILE_FLOATS)           // 9216
#define GEMM_SMEM_BYTES (3 * STAGE_FLOATS * 4)   // 110592

__global__ void __launch_bounds__(256, 1)
gemm_mma_kernel(const float* __restrict__ A, const float* __restrict__ W,
                float* __restrict__ C, int M, int N, int K)
{
    extern __shared__ float sm[];
    const uint32_t smb = smem_u32(sm);

    const int tid  = threadIdx.x;
    const int wid  = tid >> 5;
    const int lane = tid & 31;
    const int g    = lane >> 2;
    const int t    = lane & 3;
    const int wm0  = (wid >> 2) * 64;
    const int wn0  = (wid & 3) * 32;
    const int m0   = blockIdx.y * GBM;
    const int n0   = blockIdx.x * GBN;

    const int lrow = tid >> 3;             // 0..31 rows per it-step of 4
    const int lc4  = (tid & 7) << 2;       // k offset (floats)

    const float* Ag = A + (size_t)(m0 + lrow) * K + lc4;
    const float* Wg = W + (size_t)(n0 + lrow) * K + lc4;

    auto load_stage = [&](int s, int kt) {
        const int k0 = kt * GBK;
        const uint32_t sb = smb + (uint32_t)(s * STAGE_FLOATS) * 4u;
        #pragma unroll
        for (int it = 0; it < 4; it++) {
            const int row = lrow + it * 32;
            const uint32_t off = (uint32_t)(row * LDSS + lc4) * 4u;
            CP_ASYNC16(sb + off, Ag + (size_t)it * 32 * K + k0);
            CP_ASYNC16(sb + (uint32_t)TILE_FLOATS * 4u + off,
                       Wg + (size_t)it * 32 * K + k0);
        }
        CP_COMMIT();
    };

    float c[4][4][4] = {};

    const int nk = K / GBK;
    load_stage(0, 0);
    load_stage(1, 1);

    for (int kt = 0; kt < nk; kt++) {
        if (kt + 1 < nk) { CP_WAIT(1); }
        else             { CP_WAIT(0); }
        __syncthreads();

        if (kt + 2 < nk) load_stage((kt + 2) % 3, kt + 2);

        const float* Ab = sm + (kt % 3) * STAGE_FLOATS;
        const float* Wb = Ab + TILE_FLOATS;
        #pragma unroll
        for (int ks = 0; ks < 4; ks++) {
            const int k0 = ks * 8;
            uint32_t af[4][4], bf[4][2];
            #pragma unroll
            for (int i = 0; i < 4; i++) {
                const float* ap = Ab + (wm0 + i * 16 + g) * LDSS + k0 + t;
                af[i][0] = __float_as_uint(ap[0]);
                af[i][1] = __float_as_uint(ap[8 * LDSS]);
                af[i][2] = __float_as_uint(ap[4]);
                af[i][3] = __float_as_uint(ap[8 * LDSS + 4]);
            }
            #pragma unroll
            for (int j = 0; j < 4; j++) {
                const float* bp = Wb + (wn0 + j * 8 + g) * LDSS + k0 + t;
                bf[j][0] = __float_as_uint(bp[0]);
                bf[j][1] = __float_as_uint(bp[4]);
            }
            #pragma unroll
            for (int i = 0; i < 4; i++)
                #pragma unroll
                for (int j = 0; j < 4; j++)
                    mma_tf32(c[i][j], af[i], bf[j]);
        }
        __syncthreads();
    }

    #pragma unroll
    for (int i = 0; i < 4; i++) {
        #pragma unroll
        for (int j = 0; j < 4; j++) {
            const int row = m0 + wm0 + i * 16 + g;
            const int col = n0 + wn0 + j * 8 + 2 * t;
            *(float2*)(C + (size_t)row * N + col) =
                make_float2(c[i][j][0], c[i][j][1]);
            *(float2*)(C + (size_t)(row + 8) * N + col) =
                make_float2(c[i][j][2], c[i][j][3]);
        }
    }
}

// ---------------------------------------------------------------------------
// RoPE (interleaved pairs), in place, writes tf32-rounded values.
// ---------------------------------------------------------------------------
__global__ void rope_kernel(float* __restrict__ t,
                            const float* __restrict__ fcos,
                            const float* __restrict__ fsin,
                            int nh)
{
    int idx = blockIdx.x * blockDim.x + threadIdx.x;
    int total = BATCH * SEQ * nh * HALFD;
    if (idx >= total) return;
    int p = idx & (HALFD - 1);
    int h = (idx >> 5) % nh;
    int s = (idx >> 5) / nh % SEQ;
    int b = idx / (HALFD * nh * SEQ);

    float* base = t + (((size_t)(b * SEQ + s) * nh + h) * HD) + 2 * p;
    float cv = fcos[s * HALFD + p];
    float sv = fsin[s * HALFD + p];
    float x0 = base[0], x1 = base[1];
    base[0] = tf32f(x0 * cv - x1 * sv);
    base[1] = tf32f(x0 * sv + x1 * cv);
}

// ===========================================================================
// Flash attention, tf32 mma.sync, causal, GQA. Inputs pre-rounded to tf32.
// Block: 128 q-rows x 64-kv tiles, 8 warps (16 q-rows each, full kv width).
// 3-stage cp.async pipeline on K/V tiles; V used untransposed as B operand.
// Smem: 3*(K 64x68 + V 64x68) + P 128x68 = 139264 B.
// ===========================================================================
#define LDK 68
#define KV_TILE_FLOATS (64 * LDK)                    // 4352
#define ATT_SMEM_BYTES ((6 * KV_TILE_FLOATS + 128 * LDK) * 4)  // 139264

__global__ void __launch_bounds__(256, 1)
attn_mma_kernel(const float* __restrict__ q, const float* __restrict__ k,
                const float* __restrict__ v, float* __restrict__ o)
{
    extern __shared__ float sma[];
    float* Kst = sma;                            // 3 stages
    float* Vst = sma + 3 * KV_TILE_FLOATS;       // 3 stages
    float* Ps  = sma + 6 * KV_TILE_FLOATS;       // [128][LDK]
    const uint32_t Kb32 = smem_u32(Kst);
    const uint32_t Vb32 = smem_u32(Vst);

    const int qb   = blockIdx.x;
    const int h    = blockIdx.y;
    const int b    = blockIdx.z;
    const int kvh  = h / REP;
    const int tid  = threadIdx.x;
    const int wid  = tid >> 5;
    const int lane = tid & 31;
    const int g    = lane >> 2;
    const int t    = lane & 3;
    const int R0   = qb * 128 + wid * 16;
    float* Pw = Ps + (wid * 16) * LDK;

    const int lr = tid >> 2;             // kv row 0..63
    const int lc = (tid & 3) << 4;       // hd col offset 0,16,32,48
    const float* kg = k + ((size_t)b * SEQ + lr) * KVDIM + kvh * HD + lc;
    const float* vg = v + ((size_t)b * SEQ + lr) * KVDIM + kvh * HD + lc;
    const uint32_t soff = (uint32_t)(lr * LDK + lc) * 4u;

    auto load_tile = [&](int s, int ti) {
        const size_t gshift = (size_t)ti * 64 * KVDIM;
        const uint32_t kd = Kb32 + (uint32_t)(s * KV_TILE_FLOATS) * 4u + soff;
        const uint32_t vd = Vb32 + (uint32_t)(s * KV_TILE_FLOATS) * 4u + soff;
        #pragma unroll
        for (int j = 0; j < 4; j++) {
            CP_ASYNC16(kd + j * 16u, kg + gshift + j * 4);
            CP_ASYNC16(vd + j * 16u, vg + gshift + j * 4);
        }
        CP_COMMIT();
    };

    // ---- Q fragments (registers; q pre-rounded, 0.125 scale is exact) ----
    uint32_t aq[8][4];
    {
        const float* q0 = q + ((size_t)b * SEQ + R0 + g) * DIM + h * HD;
        #pragma unroll
        for (int kf = 0; kf < 8; kf++) {
            aq[kf][0] = __float_as_uint(q0[kf * 8 + t] * 0.125f);
            aq[kf][1] = __float_as_uint(q0[8 * DIM + kf * 8 + t] * 0.125f);
            aq[kf][2] = __float_as_uint(q0[kf * 8 + t + 4] * 0.125f);
            aq[kf][3] = __float_as_uint(q0[8 * DIM + kf * 8 + t + 4] * 0.125f);
        }
    }

    float co[8][4] = {};
    float mr0 = -1e30f, mr1 = -1e30f;
    float lr0 = 0.f, lr1 = 0.f;

    const int ntiles = 2 * qb + 2;
    load_tile(0, 0);
    load_tile(1, 1);

    for (int ti = 0; ti < ntiles; ti++) {
        if (ti + 1 < ntiles) { CP_WAIT(1); }
        else                 { CP_WAIT(0); }
        __syncthreads();

        if (ti + 2 < ntiles) load_tile((ti + 2) % 3, ti + 2);

        if (ti * 64 > R0 + 15) continue;   // warp entirely above diagonal

        const float* Ks = Kst + (ti % 3) * KV_TILE_FLOATS;
        const float* Vs = Vst + (ti % 3) * KV_TILE_FLOATS;

        // ---- S = Q K^T (m16 x n64, k=64) ----
        float cs[8][4] = {};
        #pragma unroll
        for (int kf = 0; kf < 8; kf++) {
            #pragma unroll
            for (int nf = 0; nf < 8; nf++) {
                uint32_t bb[2];
                bb[0] = __float_as_uint(Ks[(nf * 8 + g) * LDK + kf * 8 + t]);
                bb[1] = __float_as_uint(Ks[(nf * 8 + g) * LDK + kf * 8 + t + 4]);
                mma_tf32(cs[nf], aq[kf], bb);
            }
        }

        // ---- causal mask (partial tiles only) ----
        const int colbase = ti * 64;
        if (colbase + 63 > R0) {
            const int row0 = R0 + g, row1 = R0 + g + 8;
            #pragma unroll
            for (int nf = 0; nf < 8; nf++) {
                const int c0i = colbase + nf * 8 + 2 * t;
                if (c0i     > row0) cs[nf][0] = -1e9f;
                if (c0i + 1 > row0) cs[nf][1] = -1e9f;
                if (c0i     > row1) cs[nf][2] = -1e9f;
                if (c0i + 1 > row1) cs[nf][3] = -1e9f;
            }
        }

        // ---- online softmax (rows R0+g and R0+g+8, reduce over quad) ----
        float mx0 = -1e30f, mx1 = -1e30f;
        #pragma unroll
        for (int nf = 0; nf < 8; nf++) {
            mx0 = fmaxf(mx0, fmaxf(cs[nf][0], cs[nf][1]));
            mx1 = fmaxf(mx1, fmaxf(cs[nf][2], cs[nf][3]));
        }
        mx0 = fmaxf(mx0, __shfl_xor_sync(0xffffffffu, mx0, 1));
        mx0 = fmaxf(mx0, __shfl_xor_sync(0xffffffffu, mx0, 2));
        mx1 = fmaxf(mx1, __shfl_xor_sync(0xffffffffu, mx1, 1));
        mx1 = fmaxf(mx1, __shfl_xor_sync(0xffffffffu, mx1, 2));

        const float mn0 = fmaxf(mr0, mx0);
        const float mn1 = fmaxf(mr1, mx1);
        const float corr0 = __expf(mr0 - mn0);
        const float corr1 = __expf(mr1 - mn1);
        mr0 = mn0; mr1 = mn1;

        float rs0 = 0.f, rs1 = 0.f;
        #pragma unroll
        for (int nf = 0; nf < 8; nf++) {
            cs[nf][0] = __expf(cs[nf][0] - mn0);
            cs[nf][1] = __expf(cs[nf][1] - mn0);
            cs[nf][2] = __expf(cs[nf][2] - mn1);
            cs[nf][3] = __expf(cs[nf][3] - mn1);
            rs0 += cs[nf][0] + cs[nf][1];
            rs1 += cs[nf][2] + cs[nf][3];
        }
        rs0 += __shfl_xor_sync(0xffffffffu, rs0, 1);
        rs0 += __shfl_xor_sync(0xffffffffu, rs0, 2);
        rs1 += __shfl_xor_sync(0xffffffffu, rs1, 1);
        rs1 += __shfl_xor_sync(0xffffffffu, rs1, 2);
        lr0 = lr0 * corr0 + rs0;
        lr1 = lr1 * corr1 + rs1;
        #pragma unroll
        for (int nf = 0; nf < 8; nf++) {
            co[nf][0] *= corr0; co[nf][1] *= corr0;
            co[nf][2] *= corr1; co[nf][3] *= corr1;
        }

        // ---- P -> warp-private smem (tf32-rounded), then O += P V ----
        #pragma unroll
        for (int nf = 0; nf < 8; nf++) {
            *(float2*)(Pw + g * LDK + nf * 8 + 2 * t) =
                make_float2(tf32f(cs[nf][0]), tf32f(cs[nf][1]));
            *(float2*)(Pw + (g + 8) * LDK + nf * 8 + 2 * t) =
                make_float2(tf32f(cs[nf][2]), tf32f(cs[nf][3]));
        }
        __syncwarp();

        #pragma unroll
        for (int kf = 0; kf < 8; kf++) {
            uint32_t ap[4];
            ap[0] = __float_as_uint(Pw[g * LDK + kf * 8 + t]);
            ap[1] = __float_as_uint(Pw[(g + 8) * LDK + kf * 8 + t]);
            ap[2] = __float_as_uint(Pw[g * LDK + kf * 8 + t + 4]);
            ap[3] = __float_as_uint(Pw[(g + 8) * LDK + kf * 8 + t + 4]);
            #pragma unroll
            for (int nf = 0; nf < 8; nf++) {
                uint32_t bv[2];
                bv[0] = __float_as_uint(Vs[(kf * 8 + t) * LDK + nf * 8 + g]);
                bv[1] = __float_as_uint(Vs[(kf * 8 + t + 4) * LDK + nf * 8 + g]);
                mma_tf32(co[nf], ap, bv);
            }
        }
    }

    // ---- epilogue ----
    const float inv0 = 1.f / lr0;
    const float inv1 = 1.f / lr1;
    float* o0 = o + ((size_t)b * SEQ + R0 + g) * DIM + h * HD;
    #pragma unroll
    for (int nf = 0; nf < 8; nf++) {
        *(float2*)(o0 + nf * 8 + 2 * t) =
            make_float2(co[nf][0] * inv0, co[nf][1] * inv0);
        *(float2*)(o0 + 8 * DIM + nf * 8 + 2 * t) =
            make_float2(co[nf][2] * inv1, co[nf][3] * inv1);
    }
}

// ---------------------------------------------------------------------------
extern "C" void kernel_launch(void* const* d_in, const int* in_sizes, int n_in,
                              void* d_out, int out_size)
{
    const float* x    = (const float*)d_in[0];
    const float* fcos = (const float*)d_in[1];
    const float* fsin = (const float*)d_in[2];
    const float* wq   = (const float*)d_in[3];
    const float* wk   = (const float*)d_in[4];
    const float* wv   = (const float*)d_in[5];
    const float* wo   = (const float*)d_in[6];
    float* out = (float*)d_out;

    void *qp_, *kp_, *vp_, *op_, *xt_, *wt_;
    cudaGetSymbolAddress(&qp_, g_q);
    cudaGetSymbolAddress(&kp_, g_k);
    cudaGetSymbolAddress(&vp_, g_v);
    cudaGetSymbolAddress(&op_, g_o);
    cudaGetSymbolAddress(&xt_, g_xt);
    cudaGetSymbolAddress(&wt_, g_wt);
    float* qp = (float*)qp_;
    float* kp = (float*)kp_;
    float* vp = (float*)vp_;
    float* op = (float*)op_;
    float* xt = (float*)xt_;
    float* wt = (float*)wt_;

    const int M = BATCH * SEQ;   // 4096

    cudaFuncSetAttribute(gemm_mma_kernel,
                         cudaFuncAttributeMaxDynamicSharedMemorySize,
                         GEMM_SMEM_BYTES);
    cudaFuncSetAttribute(attn_mma_kernel,
                         cudaFuncAttributeMaxDynamicSharedMemorySize,
                         ATT_SMEM_BYTES);

    // tf32 pre-rounding of GEMM inputs
    {
        int n4;
        n4 = (BATCH * SEQ * DIM) / 4;
        tf32_round_kernel<<<(n4 + 255) / 256, 256>>>(x, xt, n4);
        n4 = (DIM * DIM) / 4;
        tf32_round_kernel<<<(n4 + 255) / 256, 256>>>(wq, wt + WQ_OFF, n4);
        n4 = (KVDIM * DIM) / 4;
        tf32_round_kernel<<<(n4 + 255) / 256, 256>>>(wk, wt + WK_OFF, n4);
        tf32_round_kernel<<<(n4 + 255) / 256, 256>>>(wv, wt + WV_OFF, n4);
        n4 = (DIM * DIM) / 4;
        tf32_round_kernel<<<(n4 + 255) / 256, 256>>>(wo, wt + WO_OFF, n4);
    }

    // QKV projections
    gemm_mma_kernel<<<dim3(DIM / GBN, M / GBM), 256, GEMM_SMEM_BYTES>>>(xt, wt + WQ_OFF, qp, M, DIM, DIM);
    gemm_mma_kernel<<<dim3(KVDIM / GBN, M / GBM), 256, GEMM_SMEM_BYTES>>>(xt, wt + WK_OFF, kp, M, KVDIM, DIM);
    gemm_mma_kernel<<<dim3(KVDIM / GBN, M / GBM), 256, GEMM_SMEM_BYTES>>>(xt, wt + WV_OFF, vp, M, KVDIM, DIM);

    // RoPE (writes tf32-rounded q, k); round v for attention
    {
        int tq = BATCH * SEQ * NH * HALFD;
        rope_kernel<<<(tq + 255) / 256, 256>>>(qp, fcos, fsin, NH);
        int tk = BATCH * SEQ * NKV * HALFD;
        rope_kernel<<<(tk + 255) / 256, 256>>>(kp, fcos, fsin, NKV);
        int n4 = (BATCH * SEQ * KVDIM) / 4;
        tf32_round_kernel<<<(n4 + 255) / 256, 256>>>(vp, vp, n4);
    }

    // attention
    attn_mma_kernel<<<dim3(SEQ / 128, NH, BATCH), 256, ATT_SMEM_BYTES>>>(qp, kp, vp, op);

    // round attention output, then output projection
    {
        int n4 = (BATCH * SEQ * DIM) / 4;
        tf32_round_kernel<<<(n4 + 255) / 256, 256>>>(op, op, n4);
    }
    gemm_mma_kernel<<<dim3(DIM / GBN, M / GBM), 256, GEMM_SMEM_BYTES>>>(op, wt + WO_OFF, out, M, DIM, DIM);
}

// round 9
// speedup vs baseline: 1.6271x; 1.6271x over previous
#include <cuda_runtime.h>
#include <cuda_fp16.h>
#include <cstdint>

#define BATCH  2
#define SEQ    2048
#define DIM    2048
#define NH     32
#define NKV    8
#define HD     64
#define KVDIM  (NKV*HD)     // 512
#define REP    (NH/NKV)     // 4
#define HALFD  (HD/2)       // 32

// ---------------- scratch (device globals; no allocations allowed) ----------
__device__ __align__(16) float  g_q [(size_t)BATCH*SEQ*NH*HD];    // fp32 q
__device__ __align__(16) float  g_k [(size_t)BATCH*SEQ*NKV*HD];   // fp32 k
__device__ __align__(16) float  g_v [(size_t)BATCH*SEQ*NKV*HD];   // fp32 v
__device__ __align__(16) float  g_o [(size_t)BATCH*SEQ*NH*HD];    // fp32 attn out
__device__ __align__(16) __half g_xh[(size_t)BATCH*SEQ*DIM];      // fp16 x
__device__ __align__(16) __half g_qh[(size_t)BATCH*SEQ*NH*HD];    // fp16 roped q (scaled)
__device__ __align__(16) __half g_kh[(size_t)BATCH*SEQ*NKV*HD];   // fp16 roped k
__device__ __align__(16) __half g_vth[(size_t)BATCH*NKV*HD*SEQ];  // fp16 V^T
__device__ __align__(16) __half g_oh[(size_t)BATCH*SEQ*NH*HD];    // fp16 attn out
__device__ __align__(16) __half g_wh[(size_t)10485760];           // fp16 weights

#define WQ_OFF 0
#define WK_OFF 4194304
#define WV_OFF 5242880
#define WO_OFF 6291456

__device__ __forceinline__ uint32_t smem_u32(const void* p) {
    uint32_t a;
    asm("{ .reg .u64 t; cvta.to.shared.u64 t, %1; cvt.u32.u64 %0, t; }"
        : "=r"(a) : "l"(p));
    return a;
}

#define CP_ASYNC16(dst, src) \
    asm volatile("cp.async.cg.shared.global [%0], [%1], 16;" \
        :: "r"(dst), "l"(src))
#define CP_COMMIT() asm volatile("cp.async.commit_group;")
#define CP_WAIT(N)  asm volatile("cp.async.wait_group %0;" :: "n"(N))

// m16n8k16 fp16 mma, fp32 accumulate. A row-major, B col-major (K-major).
__device__ __forceinline__ void mma_f16(float c[4], const uint32_t a[4],
                                        const uint32_t b[2]) {
    asm volatile(
        "mma.sync.aligned.m16n8k16.row.col.f32.f16.f16.f32 "
        "{%0,%1,%2,%3}, {%4,%5,%6,%7}, {%8,%9}, {%0,%1,%2,%3};"
        : "+f"(c[0]), "+f"(c[1]), "+f"(c[2]), "+f"(c[3])
        : "r"(a[0]), "r"(a[1]), "r"(a[2]), "r"(a[3]),
          "r"(b[0]), "r"(b[1]));
}

// ---------------------------------------------------------------------------
// fp32 -> fp16 conversion pass
// ---------------------------------------------------------------------------
__global__ void f2h_kernel(const float* __restrict__ in,
                           __half* __restrict__ out, int n4)
{
    int i = blockIdx.x * blockDim.x + threadIdx.x;
    if (i >= n4) return;
    float4 v = *(const float4*)(in + 4 * (size_t)i);
    __half2* o2 = (__half2*)(out + 4 * (size_t)i);
    o2[0] = __floats2half2_rn(v.x, v.y);
    o2[1] = __floats2half2_rn(v.z, v.w);
}

// ---------------------------------------------------------------------------
// RoPE: read fp32, write fp16 (scale folded; 0.125 for q, 1.0 for k)
// ---------------------------------------------------------------------------
__global__ void rope_h_kernel(const float* __restrict__ t,
                              __half* __restrict__ out,
                              const float* __restrict__ fcos,
                              const float* __restrict__ fsin,
                              int nh, float scale)
{
    int idx = blockIdx.x * blockDim.x + threadIdx.x;
    int total = BATCH * SEQ * nh * HALFD;
    if (idx >= total) return;
    int p = idx & (HALFD - 1);
    int h = (idx >> 5) % nh;
    int s = (idx >> 5) / nh % SEQ;
    int b = idx / (HALFD * nh * SEQ);

    size_t off = ((size_t)(b * SEQ + s) * nh + h) * HD + 2 * p;
    float cv = fcos[s * HALFD + p];
    float sv = fsin[s * HALFD + p];
    float x0 = t[off], x1 = t[off + 1];
    *(__half2*)(out + off) =
        __floats2half2_rn((x0 * cv - x1 * sv) * scale,
                          (x0 * sv + x1 * cv) * scale);
}

// ---------------------------------------------------------------------------
// V transpose+convert: v fp32 [b][s][kv*64+d] -> vt fp16 [(b*NKV+kv)*HD+d][s]
// ---------------------------------------------------------------------------
__global__ void vt_kernel(const float* __restrict__ v, __half* __restrict__ vt)
{
    __shared__ __half tile[32][33];
    const int bx = blockIdx.x;            // s tile
    const int by = blockIdx.y;            // d tile (0..1)
    const int bz = blockIdx.z;            // b*NKV+kv
    const int b  = bz / NKV, kv = bz % NKV;
    const int tx = threadIdx.x, ty = threadIdx.y;

    #pragma unroll
    for (int i = 0; i < 4; i++) {
        int s = bx * 32 + ty + i * 8;
        int d = by * 32 + tx;
        tile[ty + i * 8][tx] = __float2half_rn(
            v[(size_t)(b * SEQ + s) * KVDIM + kv * HD + d]);
    }
    __syncthreads();
    #pragma unroll
    for (int i = 0; i < 4; i++) {
        int d = by * 32 + ty + i * 8;
        int s = bx * 32 + tx;
        vt[(size_t)(bz * HD + d) * SEQ + s] = tile[tx][ty + i * 8];
    }
}

// ===========================================================================
// fp16 tensor-core GEMM: C[M,N] = A[M,K] * W[N,K]^T. A,W fp16, C fp32.
// 128x128 tile, BK=32 halves, 3-stage cp.async, 256 threads.
// Smem stride 40 halves (80B): banks (20*row + t) mod 32 all distinct.
// ===========================================================================
#define GBM 128
#define GBN 128
#define GK  32
#define LDSH 40
#define TILE_HALVES (GBM * LDSH)                 // 5120
#define STAGE_HALVES (2 * TILE_HALVES)           // 10240
#define GEMM_SMEM_BYTES (3 * STAGE_HALVES * 2)   // 61440

__global__ void __launch_bounds__(256, 1)
gemm_f16_kernel(const __half* __restrict__ A, const __half* __restrict__ W,
                float* __restrict__ C, int M, int N, int K)
{
    extern __shared__ __half smh[];
    const uint32_t smb = smem_u32(smh);

    const int tid  = threadIdx.x;
    const int wid  = tid >> 5;
    const int lane = tid & 31;
    const int g    = lane >> 2;
    const int t    = lane & 3;
    const int wm0  = (wid >> 2) * 64;
    const int wn0  = (wid & 3) * 32;
    const int m0   = blockIdx.y * GBM;
    const int n0   = blockIdx.x * GBN;

    const int lrow = tid >> 1;             // 0..127
    const int lch  = (tid & 1) * 16;       // half offset 0 or 16 within row

    const __half* Ag = A + (size_t)(m0 + lrow) * K + lch;
    const __half* Wg = W + (size_t)(n0 + lrow) * K + lch;

    auto load_stage = [&](int s, int kt) {
        const int k0 = kt * GK;
        const uint32_t sb = smb + (uint32_t)(s * STAGE_HALVES) * 2u;
        const uint32_t off = (uint32_t)(lrow * LDSH + lch) * 2u;
        CP_ASYNC16(sb + off,      Ag + k0);
        CP_ASYNC16(sb + off + 16, Ag + k0 + 8);
        CP_ASYNC16(sb + (uint32_t)TILE_HALVES * 2u + off,      Wg + k0);
        CP_ASYNC16(sb + (uint32_t)TILE_HALVES * 2u + off + 16, Wg + k0 + 8);
        CP_COMMIT();
    };

    float c[4][4][4] = {};

    const int nk = K / GK;
    load_stage(0, 0);
    load_stage(1, 1);

    for (int kt = 0; kt < nk; kt++) {
        if (kt + 1 < nk) { CP_WAIT(1); }
        else             { CP_WAIT(0); }
        __syncthreads();

        if (kt + 2 < nk) load_stage((kt + 2) % 3, kt + 2);

        const __half* Ab = smh + (kt % 3) * STAGE_HALVES;
        const __half* Wb = Ab + TILE_HALVES;
        #pragma unroll
        for (int ks = 0; ks < 2; ks++) {
            const int k0 = ks * 16;
            uint32_t af[4][4], bf[4][2];
            #pragma unroll
            for (int i = 0; i < 4; i++) {
                const __half* ap = Ab + (wm0 + i * 16 + g) * LDSH + k0 + 2 * t;
                af[i][0] = *(const uint32_t*)(ap);
                af[i][1] = *(const uint32_t*)(ap + 8 * LDSH);
                af[i][2] = *(const uint32_t*)(ap + 8);
                af[i][3] = *(const uint32_t*)(ap + 8 * LDSH + 8);
            }
            #pragma unroll
            for (int j = 0; j < 4; j++) {
                const __half* bp = Wb + (wn0 + j * 8 + g) * LDSH + k0 + 2 * t;
                bf[j][0] = *(const uint32_t*)(bp);
                bf[j][1] = *(const uint32_t*)(bp + 8);
            }
            #pragma unroll
            for (int i = 0; i < 4; i++)
                #pragma unroll
                for (int j = 0; j < 4; j++)
                    mma_f16(c[i][j], af[i], bf[j]);
        }
        __syncthreads();
    }

    #pragma unroll
    for (int i = 0; i < 4; i++) {
        #pragma unroll
        for (int j = 0; j < 4; j++) {
            const int row = m0 + wm0 + i * 16 + g;
            const int col = n0 + wn0 + j * 8 + 2 * t;
            *(float2*)(C + (size_t)row * N + col) =
                make_float2(c[i][j][0], c[i][j][1]);
            *(float2*)(C + (size_t)(row + 8) * N + col) =
                make_float2(c[i][j][2], c[i][j][3]);
        }
    }
}

// ===========================================================================
// fp16 flash attention, causal, GQA. q scaled by 0.125 already.
// Block: 128 q-rows x 64-kv tiles, 8 warps. 3-stage cp.async on K / V^T.
// Smem stride 72 halves (144B): banks (36*row + t) mod 32 = 4*row+t distinct.
// Smem: 3*64*144*2 + 128*144 = 73728 B.
// ===========================================================================
#define LDKH 72
#define KV_TILE_HALVES (64 * LDKH)                   // 4608
#define ATT_SMEM_BYTES ((6 * KV_TILE_HALVES + 128 * LDKH) * 2)  // 73728

__global__ void __launch_bounds__(256, 1)
attn_f16_kernel(const __half* __restrict__ q, const __half* __restrict__ k,
                const __half* __restrict__ vt, float* __restrict__ o)
{
    extern __shared__ __half smha[];
    __half* Kst = smha;                           // 3 stages [kv][hd]
    __half* Vst = smha + 3 * KV_TILE_HALVES;      // 3 stages [hd][kv] (V^T)
    __half* Ps  = smha + 6 * KV_TILE_HALVES;      // [128][LDKH]
    const uint32_t Kb32 = smem_u32(Kst);
    const uint32_t Vb32 = smem_u32(Vst);

    const int qb   = blockIdx.x;
    const int h    = blockIdx.y;
    const int b    = blockIdx.z;
    const int kvh  = h / REP;
    const int tid  = threadIdx.x;
    const int wid  = tid >> 5;
    const int lane = tid & 31;
    const int g    = lane >> 2;
    const int t    = lane & 3;
    const int R0   = qb * 128 + wid * 16;
    __half* Pw = Ps + (wid * 16) * LDKH;

    const int lr = tid >> 2;             // row 0..63 (kv for K, hd for Vt)
    const int lc = (tid & 3) * 16;       // half offset 0,16,32,48
    const __half* kg  = k  + ((size_t)b * SEQ + lr) * KVDIM + kvh * HD + lc;
    const __half* vtg = vt + ((size_t)(b * NKV + kvh) * HD + lr) * SEQ + lc;
    const uint32_t soff = (uint32_t)(lr * LDKH + lc) * 2u;

    auto load_tile = [&](int s, int ti) {
        const uint32_t kd = Kb32 + (uint32_t)(s * KV_TILE_HALVES) * 2u + soff;
        const uint32_t vd = Vb32 + (uint32_t)(s * KV_TILE_HALVES) * 2u + soff;
        const __half* ks = kg + (size_t)ti * 64 * KVDIM;   // advance kv rows
        const __half* vs = vtg + ti * 64;                   // advance s cols
        CP_ASYNC16(kd,      ks);
        CP_ASYNC16(kd + 16, ks + 8);
        CP_ASYNC16(vd,      vs);
        CP_ASYNC16(vd + 16, vs + 8);
        CP_COMMIT();
    };

    // ---- Q fragments from gmem (half2-aligned 32-bit loads) ----
    uint32_t aq[4][4];
    {
        const __half* q0 = q + ((size_t)b * SEQ + R0 + g) * DIM + h * HD;
        #pragma unroll
        for (int kf = 0; kf < 4; kf++) {
            const __half* qp = q0 + kf * 16 + 2 * t;
            aq[kf][0] = *(const uint32_t*)(qp);
            aq[kf][1] = *(const uint32_t*)(qp + 8 * DIM);
            aq[kf][2] = *(const uint32_t*)(qp + 8);
            aq[kf][3] = *(const uint32_t*)(qp + 8 * DIM + 8);
        }
    }

    float co[8][4] = {};
    float mr0 = -1e30f, mr1 = -1e30f;
    float lr0 = 0.f, lr1 = 0.f;

    const int ntiles = 2 * qb + 2;
    load_tile(0, 0);
    load_tile(1, 1);

    for (int ti = 0; ti < ntiles; ti++) {
        if (ti + 1 < ntiles) { CP_WAIT(1); }
        else                 { CP_WAIT(0); }
        __syncthreads();

        if (ti + 2 < ntiles) load_tile((ti + 2) % 3, ti + 2);

        if (ti * 64 > R0 + 15) continue;   // warp entirely above diagonal

        const __half* Ks = Kst + (ti % 3) * KV_TILE_HALVES;
        const __half* Vs = Vst + (ti % 3) * KV_TILE_HALVES;

        // ---- S = Q K^T (m16 x n64, k=64 in 4 chunks of 16) ----
        float cs[8][4] = {};
        #pragma unroll
        for (int kf = 0; kf < 4; kf++) {
            #pragma unroll
            for (int nf = 0; nf < 8; nf++) {
                const __half* bp = Ks + (nf * 8 + g) * LDKH + kf * 16 + 2 * t;
                uint32_t bb[2];
                bb[0] = *(const uint32_t*)(bp);
                bb[1] = *(const uint32_t*)(bp + 8);
                mma_f16(cs[nf], aq[kf], bb);
            }
        }

        // ---- causal mask (partial tiles only) ----
        const int colbase = ti * 64;
        if (colbase + 63 > R0) {
            const int row0 = R0 + g, row1 = R0 + g + 8;
            #pragma unroll
            for (int nf = 0; nf < 8; nf++) {
                const int c0i = colbase + nf * 8 + 2 * t;
                if (c0i     > row0) cs[nf][0] = -1e9f;
                if (c0i + 1 > row0) cs[nf][1] = -1e9f;
                if (c0i     > row1) cs[nf][2] = -1e9f;
                if (c0i + 1 > row1) cs[nf][3] = -1e9f;
            }
        }

        // ---- online softmax (rows R0+g, R0+g+8; reduce over quad) ----
        float mx0 = -1e30f, mx1 = -1e30f;
        #pragma unroll
        for (int nf = 0; nf < 8; nf++) {
            mx0 = fmaxf(mx0, fmaxf(cs[nf][0], cs[nf][1]));
            mx1 = fmaxf(mx1, fmaxf(cs[nf][2], cs[nf][3]));
        }
        mx0 = fmaxf(mx0, __shfl_xor_sync(0xffffffffu, mx0, 1));
        mx0 = fmaxf(mx0, __shfl_xor_sync(0xffffffffu, mx0, 2));
        mx1 = fmaxf(mx1, __shfl_xor_sync(0xffffffffu, mx1, 1));
        mx1 = fmaxf(mx1, __shfl_xor_sync(0xffffffffu, mx1, 2));

        const float mn0 = fmaxf(mr0, mx0);
        const float mn1 = fmaxf(mr1, mx1);
        const float corr0 = __expf(mr0 - mn0);
        const float corr1 = __expf(mr1 - mn1);
        mr0 = mn0; mr1 = mn1;

        float rs0 = 0.f, rs1 = 0.f;
        #pragma unroll
        for (int nf = 0; nf < 8; nf++) {
            cs[nf][0] = __expf(cs[nf][0] - mn0);
            cs[nf][1] = __expf(cs[nf][1] - mn0);
            cs[nf][2] = __expf(cs[nf][2] - mn1);
            cs[nf][3] = __expf(cs[nf][3] - mn1);
            rs0 += cs[nf][0] + cs[nf][1];
            rs1 += cs[nf][2] + cs[nf][3];
        }
        rs0 += __shfl_xor_sync(0xffffffffu, rs0, 1);
        rs0 += __shfl_xor_sync(0xffffffffu, rs0, 2);
        rs1 += __shfl_xor_sync(0xffffffffu, rs1, 1);
        rs1 += __shfl_xor_sync(0xffffffffu, rs1, 2);
        lr0 = lr0 * corr0 + rs0;
        lr1 = lr1 * corr1 + rs1;
        #pragma unroll
        for (int nf = 0; nf < 8; nf++) {
            co[nf][0] *= corr0; co[nf][1] *= corr0;
            co[nf][2] *= corr1; co[nf][3] *= corr1;
        }

        // ---- P -> warp-private smem as half2, then O += P V ----
        #pragma unroll
        for (int nf = 0; nf < 8; nf++) {
            *(__half2*)(Pw + g * LDKH + nf * 8 + 2 * t) =
                __floats2half2_rn(cs[nf][0], cs[nf][1]);
            *(__half2*)(Pw + (g + 8) * LDKH + nf * 8 + 2 * t) =
                __floats2half2_rn(cs[nf][2], cs[nf][3]);
        }
        __syncwarp();

        #pragma unroll
        for (int kf = 0; kf < 4; kf++) {
            const __half* pp = Pw + g * LDKH + kf * 16 + 2 * t;
            uint32_t ap[4];
            ap[0] = *(const uint32_t*)(pp);
            ap[1] = *(const uint32_t*)(pp + 8 * LDKH);
            ap[2] = *(const uint32_t*)(pp + 8);
            ap[3] = *(const uint32_t*)(pp + 8 * LDKH + 8);
            #pragma unroll
            for (int nf = 0; nf < 8; nf++) {
                const __half* vp = Vs + (nf * 8 + g) * LDKH + kf * 16 + 2 * t;
                uint32_t bv[2];
                bv[0] = *(const uint32_t*)(vp);
                bv[1] = *(const uint32_t*)(vp + 8);
                mma_f16(co[nf], ap, bv);
            }
        }
    }

    // ---- epilogue ----
    const float inv0 = 1.f / lr0;
    const float inv1 = 1.f / lr1;
    float* o0 = o + ((size_t)b * SEQ + R0 + g) * DIM + h * HD;
    #pragma unroll
    for (int nf = 0; nf < 8; nf++) {
        *(float2*)(o0 + nf * 8 + 2 * t) =
            make_float2(co[nf][0] * inv0, co[nf][1] * inv0);
        *(float2*)(o0 + 8 * DIM + nf * 8 + 2 * t) =
            make_float2(co[nf][2] * inv1, co[nf][3] * inv1);
    }
}

// ---------------------------------------------------------------------------
extern "C" void kernel_launch(void* const* d_in, const int* in_sizes, int n_in,
                              void* d_out, int out_size)
{
    const float* x    = (const float*)d_in[0];
    const float* fcos = (const float*)d_in[1];
    const float* fsin = (const float*)d_in[2];
    const float* wq   = (const float*)d_in[3];
    const float* wk   = (const float*)d_in[4];
    const float* wv   = (const float*)d_in[5];
    const float* wo   = (const float*)d_in[6];
    float* out = (float*)d_out;

    void *qp_, *kp_, *vp_, *op_, *xh_, *qh_, *kh_, *vth_, *oh_, *wh_;
    cudaGetSymbolAddress(&qp_, g_q);
    cudaGetSymbolAddress(&kp_, g_k);
    cudaGetSymbolAddress(&vp_, g_v);
    cudaGetSymbolAddress(&op_, g_o);
    cudaGetSymbolAddress(&xh_, g_xh);
    cudaGetSymbolAddress(&qh_, g_qh);
    cudaGetSymbolAddress(&kh_, g_kh);
    cudaGetSymbolAddress(&vth_, g_vth);
    cudaGetSymbolAddress(&oh_, g_oh);
    cudaGetSymbolAddress(&wh_, g_wh);
    float*  qp  = (float*)qp_;
    float*  kp  = (float*)kp_;
    float*  vp  = (float*)vp_;
    float*  op  = (float*)op_;
    __half* xh  = (__half*)xh_;
    __half* qh  = (__half*)qh_;
    __half* kh  = (__half*)kh_;
    __half* vth = (__half*)vth_;
    __half* oh  = (__half*)oh_;
    __half* wh  = (__half*)wh_;

    const int M = BATCH * SEQ;   // 4096

    cudaFuncSetAttribute(gemm_f16_kernel,
                         cudaFuncAttributeMaxDynamicSharedMemorySize,
                         GEMM_SMEM_BYTES);
    cudaFuncSetAttribute(attn_f16_kernel,
                         cudaFuncAttributeMaxDynamicSharedMemorySize,
                         ATT_SMEM_BYTES);

    // fp32 -> fp16 conversion of x and weights
    {
        int n4;
        n4 = (BATCH * SEQ * DIM) / 4;
        f2h_kernel<<<(n4 + 255) / 256, 256>>>(x, xh, n4);
        n4 = (DIM * DIM) / 4;
        f2h_kernel<<<(n4 + 255) / 256, 256>>>(wq, wh + WQ_OFF, n4);
        n4 = (KVDIM * DIM) / 4;
        f2h_kernel<<<(n4 + 255) / 256, 256>>>(wk, wh + WK_OFF, n4);
        f2h_kernel<<<(n4 + 255) / 256, 256>>>(wv, wh + WV_OFF, n4);
        n4 = (DIM * DIM) / 4;
        f2h_kernel<<<(n4 + 255) / 256, 256>>>(wo, wh + WO_OFF, n4);
    }

    // QKV projections (fp16 mma, fp32 out)
    gemm_f16_kernel<<<dim3(DIM / GBN, M / GBM), 256, GEMM_SMEM_BYTES>>>(xh, wh + WQ_OFF, qp, M, DIM, DIM);
    gemm_f16_kernel<<<dim3(KVDIM / GBN, M / GBM), 256, GEMM_SMEM_BYTES>>>(xh, wh + WK_OFF, kp, M, KVDIM, DIM);
    gemm_f16_kernel<<<dim3(KVDIM / GBN, M / GBM), 256, GEMM_SMEM_BYTES>>>(xh, wh + WV_OFF, vp, M, KVDIM, DIM);

    // RoPE -> fp16 (q scaled by 1/8); V transpose+convert
    {
        int tq = BATCH * SEQ * NH * HALFD;
        rope_h_kernel<<<(tq + 255) / 256, 256>>>(qp, qh, fcos, fsin, NH, 0.125f);
        int tk = BATCH * SEQ * NKV * HALFD;
        rope_h_kernel<<<(tk + 255) / 256, 256>>>(kp, kh, fcos, fsin, NKV, 1.0f);
        vt_kernel<<<dim3(SEQ / 32, HD / 32, BATCH * NKV), dim3(32, 8)>>>(vp, vth);
    }

    // attention (fp16 mma flash attention)
    attn_f16_kernel<<<dim3(SEQ / 128, NH, BATCH), 256, ATT_SMEM_BYTES>>>(qh, kh, vth, op);

    // attn out -> fp16, then output projection
    {
        int n4 = (BATCH * SEQ * DIM) / 4;
        f2h_kernel<<<(n4 + 255) / 256, 256>>>(op, oh, n4);
    }
    gemm_f16_kernel<<<dim3(DIM / GBN, M / GBM), 256, GEMM_SMEM_BYTES>>>(oh, wh + WO_OFF, out, M, DIM, DIM);
}

// round 11
// speedup vs baseline: 1.8396x; 1.1306x over previous
#include <cuda_runtime.h>
#include <cuda_fp16.h>
#include <cstdint>

#define BATCH  2
#define SEQ    2048
#define DIM    2048
#define NH     32
#define NKV    8
#define HD     64
#define KVDIM  (NKV*HD)     // 512
#define REP    (NH/NKV)     // 4
#define HALFD  (HD/2)       // 32

// ---------------- scratch (device globals; no allocations allowed) ----------
__device__ __align__(16) float  g_q [(size_t)BATCH*SEQ*NH*HD];    // fp32 q
__device__ __align__(16) float  g_k [(size_t)BATCH*SEQ*NKV*HD];   // fp32 k
__device__ __align__(16) float  g_v [(size_t)BATCH*SEQ*NKV*HD];   // fp32 v
__device__ __align__(16) __half g_xh[(size_t)BATCH*SEQ*DIM];      // fp16 x
__device__ __align__(16) __half g_qh[(size_t)BATCH*SEQ*NH*HD];    // fp16 roped q (scaled)
__device__ __align__(16) __half g_kh[(size_t)BATCH*SEQ*NKV*HD];   // fp16 roped k
__device__ __align__(16) __half g_vth[(size_t)BATCH*NKV*HD*SEQ];  // fp16 V^T
__device__ __align__(16) __half g_oh[(size_t)BATCH*SEQ*NH*HD];    // fp16 attn out
__device__ __align__(16) __half g_wh[(size_t)10485760];           // fp16 weights

#define WQ_OFF 0
#define WK_OFF 4194304
#define WV_OFF 5242880
#define WO_OFF 6291456

__device__ __forceinline__ uint32_t smem_u32(const void* p) {
    uint32_t a;
    asm("{ .reg .u64 t; cvta.to.shared.u64 t, %1; cvt.u32.u64 %0, t; }"
        : "=r"(a) : "l"(p));
    return a;
}

#define CP_ASYNC16(dst, src) \
    asm volatile("cp.async.cg.shared.global [%0], [%1], 16;" \
        :: "r"(dst), "l"(src))
#define CP_COMMIT() asm volatile("cp.async.commit_group;")
#define CP_WAIT(N)  asm volatile("cp.async.wait_group %0;" :: "n"(N))

// m16n8k16 fp16 mma, fp32 accumulate. A row-major, B col-major (K-major).
__device__ __forceinline__ void mma_f16(float c[4], const uint32_t a[4],
                                        const uint32_t b[2]) {
    asm volatile(
        "mma.sync.aligned.m16n8k16.row.col.f32.f16.f16.f32 "
        "{%0,%1,%2,%3}, {%4,%5,%6,%7}, {%8,%9}, {%0,%1,%2,%3};"
        : "+f"(c[0]), "+f"(c[1]), "+f"(c[2]), "+f"(c[3])
        : "r"(a[0]), "r"(a[1]), "r"(a[2]), "r"(a[3]),
          "r"(b[0]), "r"(b[1]));
}

// ---------------------------------------------------------------------------
// fp32 -> fp16 conversion pass
// ---------------------------------------------------------------------------
__global__ void f2h_kernel(const float* __restrict__ in,
                           __half* __restrict__ out, int n4)
{
    int i = blockIdx.x * blockDim.x + threadIdx.x;
    if (i >= n4) return;
    float4 v = *(const float4*)(in + 4 * (size_t)i);
    __half2* o2 = (__half2*)(out + 4 * (size_t)i);
    o2[0] = __floats2half2_rn(v.x, v.y);
    o2[1] = __floats2half2_rn(v.z, v.w);
}

// ---------------------------------------------------------------------------
// RoPE: read fp32, write fp16 (scale folded; 0.125 for q, 1.0 for k)
// ---------------------------------------------------------------------------
__global__ void rope_h_kernel(const float* __restrict__ t,
                              __half* __restrict__ out,
                              const float* __restrict__ fcos,
                              const float* __restrict__ fsin,
                              int nh, float scale)
{
    int idx = blockIdx.x * blockDim.x + threadIdx.x;
    int total = BATCH * SEQ * nh * HALFD;
    if (idx >= total) return;
    int p = idx & (HALFD - 1);
    int h = (idx >> 5) % nh;
    int s = (idx >> 5) / nh % SEQ;
    int b = idx / (HALFD * nh * SEQ);

    size_t off = ((size_t)(b * SEQ + s) * nh + h) * HD + 2 * p;
    float cv = fcos[s * HALFD + p];
    float sv = fsin[s * HALFD + p];
    float x0 = t[off], x1 = t[off + 1];
    *(__half2*)(out + off) =
        __floats2half2_rn((x0 * cv - x1 * sv) * scale,
                          (x0 * sv + x1 * cv) * scale);
}

// ---------------------------------------------------------------------------
// V transpose+convert: v fp32 [b][s][kv*64+d] -> vt fp16 [(b*NKV+kv)*HD+d][s]
// ---------------------------------------------------------------------------
__global__ void vt_kernel(const float* __restrict__ v, __half* __restrict__ vt)
{
    __shared__ __half tile[32][33];
    const int bx = blockIdx.x;            // s tile
    const int by = blockIdx.y;            // d tile (0..1)
    const int bz = blockIdx.z;            // b*NKV+kv
    const int b  = bz / NKV, kv = bz % NKV;
    const int tx = threadIdx.x, ty = threadIdx.y;

    #pragma unroll
    for (int i = 0; i < 4; i++) {
        int s = bx * 32 + ty + i * 8;
        int d = by * 32 + tx;
        tile[ty + i * 8][tx] = __float2half_rn(
            v[(size_t)(b * SEQ + s) * KVDIM + kv * HD + d]);
    }
    __syncthreads();
    #pragma unroll
    for (int i = 0; i < 4; i++) {
        int d = by * 32 + ty + i * 8;
        int s = bx * 32 + tx;
        vt[(size_t)(bz * HD + d) * SEQ + s] = tile[tx][ty + i * 8];
    }
}

// ===========================================================================
// fp16 tensor-core GEMM: C[M,N] = A[M,K] * W[N,K]^T. A,W fp16, C fp32.
// 128x128 tile, BK=32 halves, 3-stage cp.async, 256 threads, occupancy 2.
// Single barrier per K-chunk (3-stage ring makes the trailing sync redundant).
// ===========================================================================
#define GBM 128
#define GBN 128
#define GK  32
#define LDSH 40
#define TILE_HALVES (GBM * LDSH)                 // 5120
#define STAGE_HALVES (2 * TILE_HALVES)           // 10240
#define GEMM_SMEM_BYTES (3 * STAGE_HALVES * 2)   // 61440

__global__ void __launch_bounds__(256, 2)
gemm_f16_kernel(const __half* __restrict__ A, const __half* __restrict__ W,
                float* __restrict__ C, int M, int N, int K)
{
    extern __shared__ __half smh[];
    const uint32_t smb = smem_u32(smh);

    const int tid  = threadIdx.x;
    const int wid  = tid >> 5;
    const int lane = tid & 31;
    const int g    = lane >> 2;
    const int t    = lane & 3;
    const int wm0  = (wid >> 2) * 64;
    const int wn0  = (wid & 3) * 32;
    const int m0   = blockIdx.y * GBM;
    const int n0   = blockIdx.x * GBN;

    const int lrow = tid >> 1;             // 0..127
    const int lch  = (tid & 1) * 16;       // half offset 0 or 16 within row

    const __half* Ag = A + (size_t)(m0 + lrow) * K + lch;
    const __half* Wg = W + (size_t)(n0 + lrow) * K + lch;

    auto load_stage = [&](int s, int kt) {
        const int k0 = kt * GK;
        const uint32_t sb = smb + (uint32_t)(s * STAGE_HALVES) * 2u;
        const uint32_t off = (uint32_t)(lrow * LDSH + lch) * 2u;
        CP_ASYNC16(sb + off,      Ag + k0);
        CP_ASYNC16(sb + off + 16, Ag + k0 + 8);
        CP_ASYNC16(sb + (uint32_t)TILE_HALVES * 2u + off,      Wg + k0);
        CP_ASYNC16(sb + (uint32_t)TILE_HALVES * 2u + off + 16, Wg + k0 + 8);
        CP_COMMIT();
    };

    float c[4][4][4] = {};

    const int nk = K / GK;
    load_stage(0, 0);
    load_stage(1, 1);

    for (int kt = 0; kt < nk; kt++) {
        if (kt + 1 < nk) { CP_WAIT(1); }
        else             { CP_WAIT(0); }
        __syncthreads();   // all warps done with stage (kt+2)%3's previous life

        if (kt + 2 < nk) load_stage((kt + 2) % 3, kt + 2);

        const __half* Ab = smh + (kt % 3) * STAGE_HALVES;
        const __half* Wb = Ab + TILE_HALVES;
        #pragma unroll
        for (int ks = 0; ks < 2; ks++) {
            const int k0 = ks * 16;
            uint32_t af[4][4], bf[4][2];
            #pragma unroll
            for (int i = 0; i < 4; i++) {
                const __half* ap = Ab + (wm0 + i * 16 + g) * LDSH + k0 + 2 * t;
                af[i][0] = *(const uint32_t*)(ap);
                af[i][1] = *(const uint32_t*)(ap + 8 * LDSH);
                af[i][2] = *(const uint32_t*)(ap + 8);
                af[i][3] = *(const uint32_t*)(ap + 8 * LDSH + 8);
            }
            #pragma unroll
            for (int j = 0; j < 4; j++) {
                const __half* bp = Wb + (wn0 + j * 8 + g) * LDSH + k0 + 2 * t;
                bf[j][0] = *(const uint32_t*)(bp);
                bf[j][1] = *(const uint32_t*)(bp + 8);
            }
            #pragma unroll
            for (int i = 0; i < 4; i++)
                #pragma unroll
                for (int j = 0; j < 4; j++)
                    mma_f16(c[i][j], af[i], bf[j]);
        }
        // no trailing barrier: next iteration's CP_WAIT+sync provides the
        // ordering before this stage gets overwritten (3-stage ring).
    }

    #pragma unroll
    for (int i = 0; i < 4; i++) {
        #pragma unroll
        for (int j = 0; j < 4; j++) {
            const int row = m0 + wm0 + i * 16 + g;
            const int col = n0 + wn0 + j * 8 + 2 * t;
            *(float2*)(C + (size_t)row * N + col) =
                make_float2(c[i][j][0], c[i][j][1]);
            *(float2*)(C + (size_t)(row + 8) * N + col) =
                make_float2(c[i][j][2], c[i][j][3]);
        }
    }
}

// ===========================================================================
// fp16 flash attention, causal, GQA. q scaled by 0.125 already. fp16 output.
// Block: 128 q-rows x 64-kv tiles, 8 warps, occupancy 2.
// ===========================================================================
#define LDKH 72
#define KV_TILE_HALVES (64 * LDKH)                   // 4608
#define ATT_SMEM_BYTES ((6 * KV_TILE_HALVES + 128 * LDKH) * 2)  // 73728

__global__ void __launch_bounds__(256, 2)
attn_f16_kernel(const __half* __restrict__ q, const __half* __restrict__ k,
                const __half* __restrict__ vt, __half* __restrict__ o)
{
    extern __shared__ __half smha[];
    __half* Kst = smha;                           // 3 stages [kv][hd]
    __half* Vst = smha + 3 * KV_TILE_HALVES;      // 3 stages [hd][kv] (V^T)
    __half* Ps  = smha + 6 * KV_TILE_HALVES;      // [128][LDKH]
    const uint32_t Kb32 = smem_u32(Kst);
    const uint32_t Vb32 = smem_u32(Vst);

    const int qb   = blockIdx.x;
    const int h    = blockIdx.y;
    const int b    = blockIdx.z;
    const int kvh  = h / REP;
    const int tid  = threadIdx.x;
    const int wid  = tid >> 5;
    const int lane = tid & 31;
    const int g    = lane >> 2;
    const int t    = lane & 3;
    const int R0   = qb * 128 + wid * 16;
    __half* Pw = Ps + (wid * 16) * LDKH;

    const int lr = tid >> 2;             // row 0..63 (kv for K, hd for Vt)
    const int lc = (tid & 3) * 16;       // half offset 0,16,32,48
    const __half* kg  = k  + ((size_t)b * SEQ + lr) * KVDIM + kvh * HD + lc;
    const __half* vtg = vt + ((size_t)(b * NKV + kvh) * HD + lr) * SEQ + lc;
    const uint32_t soff = (uint32_t)(lr * LDKH + lc) * 2u;

    auto load_tile = [&](int s, int ti) {
        const uint32_t kd = Kb32 + (uint32_t)(s * KV_TILE_HALVES) * 2u + soff;
        const uint32_t vd = Vb32 + (uint32_t)(s * KV_TILE_HALVES) * 2u + soff;
        const __half* ks = kg + (size_t)ti * 64 * KVDIM;   // advance kv rows
        const __half* vs = vtg + ti * 64;                   // advance s cols
        CP_ASYNC16(kd,      ks);
        CP_ASYNC16(kd + 16, ks + 8);
        CP_ASYNC16(vd,      vs);
        CP_ASYNC16(vd + 16, vs + 8);
        CP_COMMIT();
    };

    // ---- Q fragments from gmem (half2-aligned 32-bit loads) ----
    uint32_t aq[4][4];
    {
        const __half* q0 = q + ((size_t)b * SEQ + R0 + g) * DIM + h * HD;
        #pragma unroll
        for (int kf = 0; kf < 4; kf++) {
            const __half* qp = q0 + kf * 16 + 2 * t;
            aq[kf][0] = *(const uint32_t*)(qp);
            aq[kf][1] = *(const uint32_t*)(qp + 8 * DIM);
            aq[kf][2] = *(const uint32_t*)(qp + 8);
            aq[kf][3] = *(const uint32_t*)(qp + 8 * DIM + 8);
        }
    }

    float co[8][4] = {};
    float mr0 = -1e30f, mr1 = -1e30f;
    float lr0 = 0.f, lr1 = 0.f;

    const int ntiles = 2 * qb + 2;
    load_tile(0, 0);
    load_tile(1, 1);

    for (int ti = 0; ti < ntiles; ti++) {
        if (ti + 1 < ntiles) { CP_WAIT(1); }
        else                 { CP_WAIT(0); }
        __syncthreads();

        if (ti + 2 < ntiles) load_tile((ti + 2) % 3, ti + 2);

        if (ti * 64 > R0 + 15) continue;   // warp entirely above diagonal

        const __half* Ks = Kst + (ti % 3) * KV_TILE_HALVES;
        const __half* Vs = Vst + (ti % 3) * KV_TILE_HALVES;

        // ---- S = Q K^T (m16 x n64, k=64 in 4 chunks of 16) ----
        float cs[8][4] = {};
        #pragma unroll
        for (int kf = 0; kf < 4; kf++) {
            #pragma unroll
            for (int nf = 0; nf < 8; nf++) {
                const __half* bp = Ks + (nf * 8 + g) * LDKH + kf * 16 + 2 * t;
                uint32_t bb[2];
                bb[0] = *(const uint32_t*)(bp);
                bb[1] = *(const uint32_t*)(bp + 8);
                mma_f16(cs[nf], aq[kf], bb);
            }
        }

        // ---- causal mask (partial tiles only) ----
        const int colbase = ti * 64;
        if (colbase + 63 > R0) {
            const int row0 = R0 + g, row1 = R0 + g + 8;
            #pragma unroll
            for (int nf = 0; nf < 8; nf++) {
                const int c0i = colbase + nf * 8 + 2 * t;
                if (c0i     > row0) cs[nf][0] = -1e9f;
                if (c0i + 1 > row0) cs[nf][1] = -1e9f;
                if (c0i     > row1) cs[nf][2] = -1e9f;
                if (c0i + 1 > row1) cs[nf][3] = -1e9f;
            }
        }

        // ---- online softmax (rows R0+g, R0+g+8; reduce over quad) ----
        float mx0 = -1e30f, mx1 = -1e30f;
        #pragma unroll
        for (int nf = 0; nf < 8; nf++) {
            mx0 = fmaxf(mx0, fmaxf(cs[nf][0], cs[nf][1]));
            mx1 = fmaxf(mx1, fmaxf(cs[nf][2], cs[nf][3]));
        }
        mx0 = fmaxf(mx0, __shfl_xor_sync(0xffffffffu, mx0, 1));
        mx0 = fmaxf(mx0, __shfl_xor_sync(0xffffffffu, mx0, 2));
        mx1 = fmaxf(mx1, __shfl_xor_sync(0xffffffffu, mx1, 1));
        mx1 = fmaxf(mx1, __shfl_xor_sync(0xffffffffu, mx1, 2));

        const float mn0 = fmaxf(mr0, mx0);
        const float mn1 = fmaxf(mr1, mx1);
        const float corr0 = __expf(mr0 - mn0);
        const float corr1 = __expf(mr1 - mn1);
        mr0 = mn0; mr1 = mn1;

        float rs0 = 0.f, rs1 = 0.f;
        #pragma unroll
        for (int nf = 0; nf < 8; nf++) {
            cs[nf][0] = __expf(cs[nf][0] - mn0);
            cs[nf][1] = __expf(cs[nf][1] - mn0);
            cs[nf][2] = __expf(cs[nf][2] - mn1);
            cs[nf][3] = __expf(cs[nf][3] - mn1);
            rs0 += cs[nf][0] + cs[nf][1];
            rs1 += cs[nf][2] + cs[nf][3];
        }
        rs0 += __shfl_xor_sync(0xffffffffu, rs0, 1);
        rs0 += __shfl_xor_sync(0xffffffffu, rs0, 2);
        rs1 += __shfl_xor_sync(0xffffffffu, rs1, 1);
        rs1 += __shfl_xor_sync(0xffffffffu, rs1, 2);
        lr0 = lr0 * corr0 + rs0;
        lr1 = lr1 * corr1 + rs1;
        #pragma unroll
        for (int nf = 0; nf < 8; nf++) {
            co[nf][0] *= corr0; co[nf][1] *= corr0;
            co[nf][2] *= corr1; co[nf][3] *= corr1;
        }

        // ---- P -> warp-private smem as half2, then O += P V ----
        #pragma unroll
        for (int nf = 0; nf < 8; nf++) {
            *(__half2*)(Pw + g * LDKH + nf * 8 + 2 * t) =
                __floats2half2_rn(cs[nf][0], cs[nf][1]);
            *(__half2*)(Pw + (g + 8) * LDKH + nf * 8 + 2 * t) =
                __floats2half2_rn(cs[nf][2], cs[nf][3]);
        }
        __syncwarp();

        #pragma unroll
        for (int kf = 0; kf < 4; kf++) {
            const __half* pp = Pw + g * LDKH + kf * 16 + 2 * t;
            uint32_t ap[4];
            ap[0] = *(const uint32_t*)(pp);
            ap[1] = *(const uint32_t*)(pp + 8 * LDKH);
            ap[2] = *(const uint32_t*)(pp + 8);
            ap[3] = *(const uint32_t*)(pp + 8 * LDKH + 8);
            #pragma unroll
            for (int nf = 0; nf < 8; nf++) {
                const __half* vp = Vs + (nf * 8 + g) * LDKH + kf * 16 + 2 * t;
                uint32_t bv[2];
                bv[0] = *(const uint32_t*)(vp);
                bv[1] = *(const uint32_t*)(vp + 8);
                mma_f16(co[nf], ap, bv);
            }
        }
    }

    // ---- epilogue: fp16 output (same rn rounding the f2h pass did) ----
    const float inv0 = 1.f / lr0;
    const float inv1 = 1.f / lr1;
    __half* o0 = o + ((size_t)b * SEQ + R0 + g) * DIM + h * HD;
    #pragma unroll
    for (int nf = 0; nf < 8; nf++) {
        *(__half2*)(o0 + nf * 8 + 2 * t) =
            __floats2half2_rn(co[nf][0] * inv0, co[nf][1] * inv0);
        *(__half2*)(o0 + 8 * DIM + nf * 8 + 2 * t) =
            __floats2half2_rn(co[nf][2] * inv1, co[nf][3] * inv1);
    }
}

// ---------------------------------------------------------------------------
extern "C" void kernel_launch(void* const* d_in, const int* in_sizes, int n_in,
                              void* d_out, int out_size)
{
    const float* x    = (const float*)d_in[0];
    const float* fcos = (const float*)d_in[1];
    const float* fsin = (const float*)d_in[2];
    const float* wq   = (const float*)d_in[3];
    const float* wk   = (const float*)d_in[4];
    const float* wv   = (const float*)d_in[5];
    const float* wo   = (const float*)d_in[6];
    float* out = (float*)d_out;

    void *qp_, *kp_, *vp_, *xh_, *qh_, *kh_, *vth_, *oh_, *wh_;
    cudaGetSymbolAddress(&qp_, g_q);
    cudaGetSymbolAddress(&kp_, g_k);
    cudaGetSymbolAddress(&vp_, g_v);
    cudaGetSymbolAddress(&xh_, g_xh);
    cudaGetSymbolAddress(&qh_, g_qh);
    cudaGetSymbolAddress(&kh_, g_kh);
    cudaGetSymbolAddress(&vth_, g_vth);
    cudaGetSymbolAddress(&oh_, g_oh);
    cudaGetSymbolAddress(&wh_, g_wh);
    float*  qp  = (float*)qp_;
    float*  kp  = (float*)kp_;
    float*  vp  = (float*)vp_;
    __half* xh  = (__half*)xh_;
    __half* qh  = (__half*)qh_;
    __half* kh  = (__half*)kh_;
    __half* vth = (__half*)vth_;
    __half* oh  = (__half*)oh_;
    __half* wh  = (__half*)wh_;

    const int M = BATCH * SEQ;   // 4096

    cudaFuncSetAttribute(gemm_f16_kernel,
                         cudaFuncAttributeMaxDynamicSharedMemorySize,
                         GEMM_SMEM_BYTES);
    cudaFuncSetAttribute(attn_f16_kernel,
                         cudaFuncAttributeMaxDynamicSharedMemorySize,
                         ATT_SMEM_BYTES);

    // fp32 -> fp16 conversion of x and weights
    {
        int n4;
        n4 = (BATCH * SEQ * DIM) / 4;
        f2h_kernel<<<(n4 + 255) / 256, 256>>>(x, xh, n4);
        n4 = (DIM * DIM) / 4;
        f2h_kernel<<<(n4 + 255) / 256, 256>>>(wq, wh + WQ_OFF, n4);
        n4 = (KVDIM * DIM) / 4;
        f2h_kernel<<<(n4 + 255) / 256, 256>>>(wk, wh + WK_OFF, n4);
        f2h_kernel<<<(n4 + 255) / 256, 256>>>(wv, wh + WV_OFF, n4);
        n4 = (DIM * DIM) / 4;
        f2h_kernel<<<(n4 + 255) / 256, 256>>>(wo, wh + WO_OFF, n4);
    }

    // QKV projections (fp16 mma, fp32 out)
    gemm_f16_kernel<<<dim3(DIM / GBN, M / GBM), 256, GEMM_SMEM_BYTES>>>(xh, wh + WQ_OFF, qp, M, DIM, DIM);
    gemm_f16_kernel<<<dim3(KVDIM / GBN, M / GBM), 256, GEMM_SMEM_BYTES>>>(xh, wh + WK_OFF, kp, M, KVDIM, DIM);
    gemm_f16_kernel<<<dim3(KVDIM / GBN, M / GBM), 256, GEMM_SMEM_BYTES>>>(xh, wh + WV_OFF, vp, M, KVDIM, DIM);

    // RoPE -> fp16 (q scaled by 1/8); V transpose+convert
    {
        int tq = BATCH * SEQ * NH * HALFD;
        rope_h_kernel<<<(tq + 255) / 256, 256>>>(qp, qh, fcos, fsin, NH, 0.125f);
        int tk = BATCH * SEQ * NKV * HALFD;
        rope_h_kernel<<<(tk + 255) / 256, 256>>>(kp, kh, fcos, fsin, NKV, 1.0f);
        vt_kernel<<<dim3(SEQ / 32, HD / 32, BATCH * NKV), dim3(32, 8)>>>(vp, vth);
    }

    // attention (fp16 mma flash attention, fp16 out)
    attn_f16_kernel<<<dim3(SEQ / 128, NH, BATCH), 256, ATT_SMEM_BYTES>>>(qh, kh, vth, oh);

    // output projection
    gemm_f16_kernel<<<dim3(DIM / GBN, M / GBM), 256, GEMM_SMEM_BYTES>>>(oh, wh + WO_OFF, out, M, DIM, DIM);
}

// round 12
// speedup vs baseline: 1.8794x; 1.0216x over previous
#include <cuda_runtime.h>
#include <cuda_fp16.h>
#include <cstdint>

#define BATCH  2
#define SEQ    2048
#define DIM    2048
#define NH     32
#define NKV    8
#define HD     64
#define KVDIM  (NKV*HD)     // 512
#define REP    (NH/NKV)     // 4
#define HALFD  (HD/2)       // 32
#define QKVD   (DIM + 2*KVDIM)   // 3072 fused projection width
#define KCOL   DIM               // 2048: k column base in fused buffer
#define VCOL   (DIM + KVDIM)     // 2560: v column base

// ---------------- scratch (device globals; no allocations allowed) ----------
__device__ __align__(16) float  g_qkv[(size_t)BATCH*SEQ*QKVD];    // fp32 fused qkv (50MB)
__device__ __align__(16) __half g_xh[(size_t)BATCH*SEQ*DIM];      // fp16 x
__device__ __align__(16) __half g_qh[(size_t)BATCH*SEQ*NH*HD];    // fp16 roped q (scaled)
__device__ __align__(16) __half g_kh[(size_t)BATCH*SEQ*NKV*HD];   // fp16 roped k
__device__ __align__(16) __half g_vth[(size_t)BATCH*NKV*HD*SEQ];  // fp16 V^T
__device__ __align__(16) __half g_oh[(size_t)BATCH*SEQ*NH*HD];    // fp16 attn out
__device__ __align__(16) __half g_wh[(size_t)10485760];           // fp16 weights

#define WQ_OFF 0                  // rows [0,2048)   of fused W
#define WK_OFF 4194304            // rows [2048,2560)
#define WV_OFF 5242880            // rows [2560,3072)  (contiguous => fused W)
#define WO_OFF 6291456

__device__ __forceinline__ uint32_t smem_u32(const void* p) {
    uint32_t a;
    asm("{ .reg .u64 t; cvta.to.shared.u64 t, %1; cvt.u32.u64 %0, t; }"
        : "=r"(a) : "l"(p));
    return a;
}

#define CP_ASYNC16(dst, src) \
    asm volatile("cp.async.cg.shared.global [%0], [%1], 16;" \
        :: "r"(dst), "l"(src))
#define CP_COMMIT() asm volatile("cp.async.commit_group;")
#define CP_WAIT(N)  asm volatile("cp.async.wait_group %0;" :: "n"(N))

// m16n8k16 fp16 mma, fp32 accumulate. A row-major, B col-major (K-major).
__device__ __forceinline__ void mma_f16(float c[4], const uint32_t a[4],
                                        const uint32_t b[2]) {
    asm volatile(
        "mma.sync.aligned.m16n8k16.row.col.f32.f16.f16.f32 "
        "{%0,%1,%2,%3}, {%4,%5,%6,%7}, {%8,%9}, {%0,%1,%2,%3};"
        : "+f"(c[0]), "+f"(c[1]), "+f"(c[2]), "+f"(c[3])
        : "r"(a[0]), "r"(a[1]), "r"(a[2]), "r"(a[3]),
          "r"(b[0]), "r"(b[1]));
}

// ---------------------------------------------------------------------------
// fp32 -> fp16 conversion pass
// ---------------------------------------------------------------------------
__global__ void f2h_kernel(const float* __restrict__ in,
                           __half* __restrict__ out, int n4)
{
    int i = blockIdx.x * blockDim.x + threadIdx.x;
    if (i >= n4) return;
    float4 v = *(const float4*)(in + 4 * (size_t)i);
    __half2* o2 = (__half2*)(out + 4 * (size_t)i);
    o2[0] = __floats2half2_rn(v.x, v.y);
    o2[1] = __floats2half2_rn(v.z, v.w);
}

// ---------------------------------------------------------------------------
// RoPE from fused qkv buffer (row stride QKVD, column base cb) -> fp16 packed
// ---------------------------------------------------------------------------
__global__ void rope_h_kernel(const float* __restrict__ t,
                              __half* __restrict__ out,
                              const float* __restrict__ fcos,
                              const float* __restrict__ fsin,
                              int nh, float scale, int cb)
{
    int idx = blockIdx.x * blockDim.x + threadIdx.x;
    int total = BATCH * SEQ * nh * HALFD;
    if (idx >= total) return;
    int p = idx & (HALFD - 1);
    int h = (idx >> 5) % nh;
    int s = (idx >> 5) / nh % SEQ;
    int b = idx / (HALFD * nh * SEQ);

    size_t in_off  = (size_t)(b * SEQ + s) * QKVD + cb + h * HD + 2 * p;
    size_t out_off = ((size_t)(b * SEQ + s) * nh + h) * HD + 2 * p;
    float cv = fcos[s * HALFD + p];
    float sv = fsin[s * HALFD + p];
    float x0 = t[in_off], x1 = t[in_off + 1];
    *(__half2*)(out + out_off) =
        __floats2half2_rn((x0 * cv - x1 * sv) * scale,
                          (x0 * sv + x1 * cv) * scale);
}

// ---------------------------------------------------------------------------
// V transpose+convert from fused qkv: col base VCOL, row stride QKVD
//   -> vt fp16 [(b*NKV+kv)*HD+d][s]
// ---------------------------------------------------------------------------
__global__ void vt_kernel(const float* __restrict__ qkv, __half* __restrict__ vt)
{
    __shared__ __half tile[32][33];
    const int bx = blockIdx.x;            // s tile
    const int by = blockIdx.y;            // d tile (0..1)
    const int bz = blockIdx.z;            // b*NKV+kv
    const int b  = bz / NKV, kv = bz % NKV;
    const int tx = threadIdx.x, ty = threadIdx.y;

    #pragma unroll
    for (int i = 0; i < 4; i++) {
        int s = bx * 32 + ty + i * 8;
        int d = by * 32 + tx;
        tile[ty + i * 8][tx] = __float2half_rn(
            qkv[(size_t)(b * SEQ + s) * QKVD + VCOL + kv * HD + d]);
    }
    __syncthreads();
    #pragma unroll
    for (int i = 0; i < 4; i++) {
        int d = by * 32 + ty + i * 8;
        int s = bx * 32 + tx;
        vt[(size_t)(bz * HD + d) * SEQ + s] = tile[tx][ty + i * 8];
    }
}

// ===========================================================================
// fp16 tensor-core GEMM: C[M,N] = A[M,K] * W[N,K]^T. A,W fp16, C fp32.
// 128x128 tile, BK=32 halves, 3-stage cp.async, 256 threads, occupancy 2.
// ===========================================================================
#define GBM 128
#define GBN 128
#define GK  32
#define LDSH 40
#define TILE_HALVES (GBM * LDSH)                 // 5120
#define STAGE_HALVES (2 * TILE_HALVES)           // 10240
#define GEMM_SMEM_BYTES (3 * STAGE_HALVES * 2)   // 61440

__global__ void __launch_bounds__(256, 2)
gemm_f16_kernel(const __half* __restrict__ A, const __half* __restrict__ W,
                float* __restrict__ C, int M, int N, int K)
{
    extern __shared__ __half smh[];
    const uint32_t smb = smem_u32(smh);

    const int tid  = threadIdx.x;
    const int wid  = tid >> 5;
    const int lane = tid & 31;
    const int g    = lane >> 2;
    const int t    = lane & 3;
    const int wm0  = (wid >> 2) * 64;
    const int wn0  = (wid & 3) * 32;
    const int m0   = blockIdx.y * GBM;
    const int n0   = blockIdx.x * GBN;

    const int lrow = tid >> 1;             // 0..127
    const int lch  = (tid & 1) * 16;       // half offset 0 or 16 within row

    const __half* Ag = A + (size_t)(m0 + lrow) * K + lch;
    const __half* Wg = W + (size_t)(n0 + lrow) * K + lch;

    auto load_stage = [&](int s, int kt) {
        const int k0 = kt * GK;
        const uint32_t sb = smb + (uint32_t)(s * STAGE_HALVES) * 2u;
        const uint32_t off = (uint32_t)(lrow * LDSH + lch) * 2u;
        CP_ASYNC16(sb + off,      Ag + k0);
        CP_ASYNC16(sb + off + 16, Ag + k0 + 8);
        CP_ASYNC16(sb + (uint32_t)TILE_HALVES * 2u + off,      Wg + k0);
        CP_ASYNC16(sb + (uint32_t)TILE_HALVES * 2u + off + 16, Wg + k0 + 8);
        CP_COMMIT();
    };

    float c[4][4][4] = {};

    const int nk = K / GK;
    load_stage(0, 0);
    load_stage(1, 1);

    for (int kt = 0; kt < nk; kt++) {
        if (kt + 1 < nk) { CP_WAIT(1); }
        else             { CP_WAIT(0); }
        __syncthreads();   // all warps done with stage (kt+2)%3's previous life

        if (kt + 2 < nk) load_stage((kt + 2) % 3, kt + 2);

        const __half* Ab = smh + (kt % 3) * STAGE_HALVES;
        const __half* Wb = Ab + TILE_HALVES;
        #pragma unroll
        for (int ks = 0; ks < 2; ks++) {
            const int k0 = ks * 16;
            uint32_t af[4][4], bf[4][2];
            #pragma unroll
            for (int i = 0; i < 4; i++) {
                const __half* ap = Ab + (wm0 + i * 16 + g) * LDSH + k0 + 2 * t;
                af[i][0] = *(const uint32_t*)(ap);
                af[i][1] = *(const uint32_t*)(ap + 8 * LDSH);
                af[i][2] = *(const uint32_t*)(ap + 8);
                af[i][3] = *(const uint32_t*)(ap + 8 * LDSH + 8);
            }
            #pragma unroll
            for (int j = 0; j < 4; j++) {
                const __half* bp = Wb + (wn0 + j * 8 + g) * LDSH + k0 + 2 * t;
                bf[j][0] = *(const uint32_t*)(bp);
                bf[j][1] = *(const uint32_t*)(bp + 8);
            }
            #pragma unroll
            for (int i = 0; i < 4; i++)
                #pragma unroll
                for (int j = 0; j < 4; j++)
                    mma_f16(c[i][j], af[i], bf[j]);
        }
    }

    #pragma unroll
    for (int i = 0; i < 4; i++) {
        #pragma unroll
        for (int j = 0; j < 4; j++) {
            const int row = m0 + wm0 + i * 16 + g;
            const int col = n0 + wn0 + j * 8 + 2 * t;
            *(float2*)(C + (size_t)row * N + col) =
                make_float2(c[i][j][0], c[i][j][1]);
            *(float2*)(C + (size_t)(row + 8) * N + col) =
                make_float2(c[i][j][2], c[i][j][3]);
        }
    }
}

// ===========================================================================
// fp16 flash attention, causal, GQA. q scaled by 0.125 already. fp16 output.
// Block: 128 q-rows x 64-kv tiles, 8 warps, occupancy 2.
// ===========================================================================
#define LDKH 72
#define KV_TILE_HALVES (64 * LDKH)                   // 4608
#define ATT_SMEM_BYTES ((6 * KV_TILE_HALVES + 128 * LDKH) * 2)  // 73728

__global__ void __launch_bounds__(256, 2)
attn_f16_kernel(const __half* __restrict__ q, const __half* __restrict__ k,
                const __half* __restrict__ vt, __half* __restrict__ o)
{
    extern __shared__ __half smha[];
    __half* Kst = smha;                           // 3 stages [kv][hd]
    __half* Vst = smha + 3 * KV_TILE_HALVES;      // 3 stages [hd][kv] (V^T)
    __half* Ps  = smha + 6 * KV_TILE_HALVES;      // [128][LDKH]
    const uint32_t Kb32 = smem_u32(Kst);
    const uint32_t Vb32 = smem_u32(Vst);

    const int qb   = blockIdx.x;
    const int h    = blockIdx.y;
    const int b    = blockIdx.z;
    const int kvh  = h / REP;
    const int tid  = threadIdx.x;
    const int wid  = tid >> 5;
    const int lane = tid & 31;
    const int g    = lane >> 2;
    const int t    = lane & 3;
    const int R0   = qb * 128 + wid * 16;
    __half* Pw = Ps + (wid * 16) * LDKH;

    const int lr = tid >> 2;             // row 0..63 (kv for K, hd for Vt)
    const int lc = (tid & 3) * 16;       // half offset 0,16,32,48
    const __half* kg  = k  + ((size_t)b * SEQ + lr) * KVDIM + kvh * HD + lc;
    const __half* vtg = vt + ((size_t)(b * NKV + kvh) * HD + lr) * SEQ + lc;
    const uint32_t soff = (uint32_t)(lr * LDKH + lc) * 2u;

    auto load_tile = [&](int s, int ti) {
        const uint32_t kd = Kb32 + (uint32_t)(s * KV_TILE_HALVES) * 2u + soff;
        const uint32_t vd = Vb32 + (uint32_t)(s * KV_TILE_HALVES) * 2u + soff;
        const __half* ks = kg + (size_t)ti * 64 * KVDIM;   // advance kv rows
        const __half* vs = vtg + ti * 64;                   // advance s cols
        CP_ASYNC16(kd,      ks);
        CP_ASYNC16(kd + 16, ks + 8);
        CP_ASYNC16(vd,      vs);
        CP_ASYNC16(vd + 16, vs + 8);
        CP_COMMIT();
    };

    // ---- Q fragments from gmem (half2-aligned 32-bit loads) ----
    uint32_t aq[4][4];
    {
        const __half* q0 = q + ((size_t)b * SEQ + R0 + g) * DIM + h * HD;
        #pragma unroll
        for (int kf = 0; kf < 4; kf++) {
            const __half* qp = q0 + kf * 16 + 2 * t;
            aq[kf][0] = *(const uint32_t*)(qp);
            aq[kf][1] = *(const uint32_t*)(qp + 8 * DIM);
            aq[kf][2] = *(const uint32_t*)(qp + 8);
            aq[kf][3] = *(const uint32_t*)(qp + 8 * DIM + 8);
        }
    }

    float co[8][4] = {};
    float mr0 = -1e30f, mr1 = -1e30f;
    float lr0 = 0.f, lr1 = 0.f;

    const int ntiles = 2 * qb + 2;
    load_tile(0, 0);
    load_tile(1, 1);

    for (int ti = 0; ti < ntiles; ti++) {
        if (ti + 1 < ntiles) { CP_WAIT(1); }
        else                 { CP_WAIT(0); }
        __syncthreads();

        if (ti + 2 < ntiles) load_tile((ti + 2) % 3, ti + 2);

        if (ti * 64 > R0 + 15) continue;   // warp entirely above diagonal

        const __half* Ks = Kst + (ti % 3) * KV_TILE_HALVES;
        const __half* Vs = Vst + (ti % 3) * KV_TILE_HALVES;

        // ---- S = Q K^T (m16 x n64, k=64 in 4 chunks of 16) ----
        float cs[8][4] = {};
        #pragma unroll
        for (int kf = 0; kf < 4; kf++) {
            #pragma unroll
            for (int nf = 0; nf < 8; nf++) {
                const __half* bp = Ks + (nf * 8 + g) * LDKH + kf * 16 + 2 * t;
                uint32_t bb[2];
                bb[0] = *(const uint32_t*)(bp);
                bb[1] = *(const uint32_t*)(bp + 8);
                mma_f16(cs[nf], aq[kf], bb);
            }
        }

        // ---- causal mask (partial tiles only) ----
        const int colbase = ti * 64;
        if (colbase + 63 > R0) {
            const int row0 = R0 + g, row1 = R0 + g + 8;
            #pragma unroll
            for (int nf = 0; nf < 8; nf++) {
                const int c0i = colbase + nf * 8 + 2 * t;
                if (c0i     > row0) cs[nf][0] = -1e9f;
                if (c0i + 1 > row0) cs[nf][1] = -1e9f;
                if (c0i     > row1) cs[nf][2] = -1e9f;
                if (c0i + 1 > row1) cs[nf][3] = -1e9f;
            }
        }

        // ---- online softmax (rows R0+g, R0+g+8; reduce over quad) ----
        float mx0 = -1e30f, mx1 = -1e30f;
        #pragma unroll
        for (int nf = 0; nf < 8; nf++) {
            mx0 = fmaxf(mx0, fmaxf(cs[nf][0], cs[nf][1]));
            mx1 = fmaxf(mx1, fmaxf(cs[nf][2], cs[nf][3]));
        }
        mx0 = fmaxf(mx0, __shfl_xor_sync(0xffffffffu, mx0, 1));
        mx0 = fmaxf(mx0, __shfl_xor_sync(0xffffffffu, mx0, 2));
        mx1 = fmaxf(mx1, __shfl_xor_sync(0xffffffffu, mx1, 1));
        mx1 = fmaxf(mx1, __shfl_xor_sync(0xffffffffu, mx1, 2));

        const float mn0 = fmaxf(mr0, mx0);
        const float mn1 = fmaxf(mr1, mx1);
        const float corr0 = __expf(mr0 - mn0);
        const float corr1 = __expf(mr1 - mn1);
        mr0 = mn0; mr1 = mn1;

        float rs0 = 0.f, rs1 = 0.f;
        #pragma unroll
        for (int nf = 0; nf < 8; nf++) {
            cs[nf][0] = __expf(cs[nf][0] - mn0);
            cs[nf][1] = __expf(cs[nf][1] - mn0);
            cs[nf][2] = __expf(cs[nf][2] - mn1);
            cs[nf][3] = __expf(cs[nf][3] - mn1);
            rs0 += cs[nf][0] + cs[nf][1];
            rs1 += cs[nf][2] + cs[nf][3];
        }
        rs0 += __shfl_xor_sync(0xffffffffu, rs0, 1);
        rs0 += __shfl_xor_sync(0xffffffffu, rs0, 2);
        rs1 += __shfl_xor_sync(0xffffffffu, rs1, 1);
        rs1 += __shfl_xor_sync(0xffffffffu, rs1, 2);
        lr0 = lr0 * corr0 + rs0;
        lr1 = lr1 * corr1 + rs1;
        #pragma unroll
        for (int nf = 0; nf < 8; nf++) {
            co[nf][0] *= corr0; co[nf][1] *= corr0;
            co[nf][2] *= corr1; co[nf][3] *= corr1;
        }

        // ---- P -> warp-private smem as half2, then O += P V ----
        #pragma unroll
        for (int nf = 0; nf < 8; nf++) {
            *(__half2*)(Pw + g * LDKH + nf * 8 + 2 * t) =
                __floats2half2_rn(cs[nf][0], cs[nf][1]);
            *(__half2*)(Pw + (g + 8) * LDKH + nf * 8 + 2 * t) =
                __floats2half2_rn(cs[nf][2], cs[nf][3]);
        }
        __syncwarp();

        #pragma unroll
        for (int kf = 0; kf < 4; kf++) {
            const __half* pp = Pw + g * LDKH + kf * 16 + 2 * t;
            uint32_t ap[4];
            ap[0] = *(const uint32_t*)(pp);
            ap[1] = *(const uint32_t*)(pp + 8 * LDKH);
            ap[2] = *(const uint32_t*)(pp + 8);
            ap[3] = *(const uint32_t*)(pp + 8 * LDKH + 8);
            #pragma unroll
            for (int nf = 0; nf < 8; nf++) {
                const __half* vp = Vs + (nf * 8 + g) * LDKH + kf * 16 + 2 * t;
                uint32_t bv[2];
                bv[0] = *(const uint32_t*)(vp);
                bv[1] = *(const uint32_t*)(vp + 8);
                mma_f16(co[nf], ap, bv);
            }
        }
    }

    // ---- epilogue: fp16 output ----
    const float inv0 = 1.f / lr0;
    const float inv1 = 1.f / lr1;
    __half* o0 = o + ((size_t)b * SEQ + R0 + g) * DIM + h * HD;
    #pragma unroll
    for (int nf = 0; nf < 8; nf++) {
        *(__half2*)(o0 + nf * 8 + 2 * t) =
            __floats2half2_rn(co[nf][0] * inv0, co[nf][1] * inv0);
        *(__half2*)(o0 + 8 * DIM + nf * 8 + 2 * t) =
            __floats2half2_rn(co[nf][2] * inv1, co[nf][3] * inv1);
    }
}

// ---------------------------------------------------------------------------
extern "C" void kernel_launch(void* const* d_in, const int* in_sizes, int n_in,
                              void* d_out, int out_size)
{
    const float* x    = (const float*)d_in[0];
    const float* fcos = (const float*)d_in[1];
    const float* fsin = (const float*)d_in[2];
    const float* wq   = (const float*)d_in[3];
    const float* wk   = (const float*)d_in[4];
    const float* wv   = (const float*)d_in[5];
    const float* wo   = (const float*)d_in[6];
    float* out = (float*)d_out;

    void *qkv_, *xh_, *qh_, *kh_, *vth_, *oh_, *wh_;
    cudaGetSymbolAddress(&qkv_, g_qkv);
    cudaGetSymbolAddress(&xh_, g_xh);
    cudaGetSymbolAddress(&qh_, g_qh);
    cudaGetSymbolAddress(&kh_, g_kh);
    cudaGetSymbolAddress(&vth_, g_vth);
    cudaGetSymbolAddress(&oh_, g_oh);
    cudaGetSymbolAddress(&wh_, g_wh);
    float*  qkv = (float*)qkv_;
    __half* xh  = (__half*)xh_;
    __half* qh  = (__half*)qh_;
    __half* kh  = (__half*)kh_;
    __half* vth = (__half*)vth_;
    __half* oh  = (__half*)oh_;
    __half* wh  = (__half*)wh_;

    const int M = BATCH * SEQ;   // 4096

    cudaFuncSetAttribute(gemm_f16_kernel,
                         cudaFuncAttributeMaxDynamicSharedMemorySize,
                         GEMM_SMEM_BYTES);
    cudaFuncSetAttribute(attn_f16_kernel,
                         cudaFuncAttributeMaxDynamicSharedMemorySize,
                         ATT_SMEM_BYTES);

    // fp32 -> fp16 conversion of x and weights (wq|wk|wv land contiguously)
    {
        int n4;
        n4 = (BATCH * SEQ * DIM) / 4;
        f2h_kernel<<<(n4 + 255) / 256, 256>>>(x, xh, n4);
        n4 = (DIM * DIM) / 4;
        f2h_kernel<<<(n4 + 255) / 256, 256>>>(wq, wh + WQ_OFF, n4);
        n4 = (KVDIM * DIM) / 4;
        f2h_kernel<<<(n4 + 255) / 256, 256>>>(wk, wh + WK_OFF, n4);
        f2h_kernel<<<(n4 + 255) / 256, 256>>>(wv, wh + WV_OFF, n4);
        n4 = (DIM * DIM) / 4;
        f2h_kernel<<<(n4 + 255) / 256, 256>>>(wo, wh + WO_OFF, n4);
    }

    // Fused QKV projection: one GEMM, N = 3072 (wq|wk|wv rows contiguous)
    gemm_f16_kernel<<<dim3(QKVD / GBN, M / GBM), 256, GEMM_SMEM_BYTES>>>(
        xh, wh, qkv, M, QKVD, DIM);

    // RoPE -> fp16 (q scaled by 1/8) from fused buffer; V transpose+convert
    {
        int tq = BATCH * SEQ * NH * HALFD;
        rope_h_kernel<<<(tq + 255) / 256, 256>>>(qkv, qh, fcos, fsin, NH, 0.125f, 0);
        int tk = BATCH * SEQ * NKV * HALFD;
        rope_h_kernel<<<(tk + 255) / 256, 256>>>(qkv, kh, fcos, fsin, NKV, 1.0f, KCOL);
        vt_kernel<<<dim3(SEQ / 32, HD / 32, BATCH * NKV), dim3(32, 8)>>>(qkv, vth);
    }

    // attention (fp16 mma flash attention, fp16 out)
    attn_f16_kernel<<<dim3(SEQ / 128, NH, BATCH), 256, ATT_SMEM_BYTES>>>(qh, kh, vth, oh);

    // output projection
    gemm_f16_kernel<<<dim3(DIM / GBN, M / GBM), 256, GEMM_SMEM_BYTES>>>(oh, wh + WO_OFF, out, M, DIM, DIM);
}

// round 15
// speedup vs baseline: 1.9690x; 1.0477x over previous
#include <cuda_runtime.h>
#include <cuda_fp16.h>
#include <cstdint>

#define BATCH  2
#define SEQ    2048
#define DIM    2048
#define NH     32
#define NKV    8
#define HD     64
#define KVDIM  (NKV*HD)     // 512
#define REP    (NH/NKV)     // 4
#define HALFD  (HD/2)       // 32
#define QKVD   (DIM + 2*KVDIM)   // 3072 fused projection width
#define KCOL   DIM               // 2048: k column base in fused buffer
#define VCOL   (DIM + KVDIM)     // 2560: v column base

// ---------------- scratch (device globals; no allocations allowed) ----------
__device__ __align__(16) float  g_qkv[(size_t)BATCH*SEQ*QKVD];    // fp32 fused qkv
__device__ __align__(16) __half g_xh[(size_t)BATCH*SEQ*DIM];      // fp16 x
__device__ __align__(16) __half g_qh[(size_t)BATCH*SEQ*NH*HD];    // fp16 roped q (scaled)
__device__ __align__(16) __half g_kh[(size_t)BATCH*SEQ*NKV*HD];   // fp16 roped k
__device__ __align__(16) __half g_vth[(size_t)BATCH*NKV*HD*SEQ];  // fp16 V^T
__device__ __align__(16) __half g_oh[(size_t)BATCH*SEQ*NH*HD];    // fp16 attn out
__device__ __align__(16) __half g_wh[(size_t)10485760];           // fp16 weights

#define WQ_OFF 0
#define WK_OFF 4194304
#define WV_OFF 5242880
#define WO_OFF 6291456

__device__ __forceinline__ uint32_t smem_u32(const void* p) {
    uint32_t a;
    asm("{ .reg .u64 t; cvta.to.shared.u64 t, %1; cvt.u32.u64 %0, t; }"
        : "=r"(a) : "l"(p));
    return a;
}

#define CP_ASYNC16(dst, src) \
    asm volatile("cp.async.cg.shared.global [%0], [%1], 16;" \
        :: "r"(dst), "l"(src))
#define CP_COMMIT() asm volatile("cp.async.commit_group;")
#define CP_WAIT(N)  asm volatile("cp.async.wait_group %0;" :: "n"(N))

// ldmatrix: four/two 8x8 b16 matrices; lane k of group i supplies row-k addr
__device__ __forceinline__ void ldsm_x4(uint32_t r[4], uint32_t addr) {
    asm volatile("ldmatrix.sync.aligned.m8n8.x4.shared.b16 {%0,%1,%2,%3}, [%4];"
        : "=r"(r[0]), "=r"(r[1]), "=r"(r[2]), "=r"(r[3]) : "r"(addr));
}
__device__ __forceinline__ void ldsm_x2(uint32_t r[2], uint32_t addr) {
    asm volatile("ldmatrix.sync.aligned.m8n8.x2.shared.b16 {%0,%1}, [%2];"
        : "=r"(r[0]), "=r"(r[1]) : "r"(addr));
}

// m16n8k16 fp16 mma, fp32 accumulate. A row-major, B col-major (K-major).
__device__ __forceinline__ void mma_f16(float c[4], const uint32_t a[4],
                                        const uint32_t b[2]) {
    asm volatile(
        "mma.sync.aligned.m16n8k16.row.col.f32.f16.f16.f32 "
        "{%0,%1,%2,%3}, {%4,%5,%6,%7}, {%8,%9}, {%0,%1,%2,%3};"
        : "+f"(c[0]), "+f"(c[1]), "+f"(c[2]), "+f"(c[3])
        : "r"(a[0]), "r"(a[1]), "r"(a[2]), "r"(a[3]),
          "r"(b[0]), "r"(b[1]));
}

// ---------------------------------------------------------------------------
// fp32 -> fp16 conversion pass
// ---------------------------------------------------------------------------
__global__ void f2h_kernel(const float* __restrict__ in,
                           __half* __restrict__ out, int n4)
{
    int i = blockIdx.x * blockDim.x + threadIdx.x;
    if (i >= n4) return;
    float4 v = *(const float4*)(in + 4 * (size_t)i);
    __half2* o2 = (__half2*)(out + 4 * (size_t)i);
    o2[0] = __floats2half2_rn(v.x, v.y);
    o2[1] = __floats2half2_rn(v.z, v.w);
}

// ---------------------------------------------------------------------------
// RoPE from fused qkv buffer (row stride QKVD, column base cb) -> fp16 packed
// ---------------------------------------------------------------------------
__global__ void rope_h_kernel(const float* __restrict__ t,
                              __half* __restrict__ out,
                              const float* __restrict__ fcos,
                              const float* __restrict__ fsin,
                              int nh, float scale, int cb)
{
    int idx = blockIdx.x * blockDim.x + threadIdx.x;
    int total = BATCH * SEQ * nh * HALFD;
    if (idx >= total) return;
    int p = idx & (HALFD - 1);
    int h = (idx >> 5) % nh;
    int s = (idx >> 5) / nh % SEQ;
    int b = idx / (HALFD * nh * SEQ);

    size_t in_off  = (size_t)(b * SEQ + s) * QKVD + cb + h * HD + 2 * p;
    size_t out_off = ((size_t)(b * SEQ + s) * nh + h) * HD + 2 * p;
    float cv = fcos[s * HALFD + p];
    float sv = fsin[s * HALFD + p];
    float x0 = t[in_off], x1 = t[in_off + 1];
    *(__half2*)(out + out_off) =
        __floats2half2_rn((x0 * cv - x1 * sv) * scale,
                          (x0 * sv + x1 * cv) * scale);
}

// ---------------------------------------------------------------------------
// V transpose+convert from fused qkv -> vt fp16 [(b*NKV+kv)*HD+d][s]
// ---------------------------------------------------------------------------
__global__ void vt_kernel(const float* __restrict__ qkv, __half* __restrict__ vt)
{
    __shared__ __half tile[32][33];
    const int bx = blockIdx.x;
    const int by = blockIdx.y;
    const int bz = blockIdx.z;
    const int b  = bz / NKV, kv = bz % NKV;
    const int tx = threadIdx.x, ty = threadIdx.y;

    #pragma unroll
    for (int i = 0; i < 4; i++) {
        int s = bx * 32 + ty + i * 8;
        int d = by * 32 + tx;
        tile[ty + i * 8][tx] = __float2half_rn(
            qkv[(size_t)(b * SEQ + s) * QKVD + VCOL + kv * HD + d]);
    }
    __syncthreads();
    #pragma unroll
    for (int i = 0; i < 4; i++) {
        int d = by * 32 + ty + i * 8;
        int s = bx * 32 + tx;
        vt[(size_t)(bz * HD + d) * SEQ + s] = tile[tx][ty + i * 8];
    }
}

// ===========================================================================
// fp16 tensor-core GEMM with ldmatrix fragment loads.
// ===========================================================================
#define GBM 128
#define GBN 128
#define GK  32
#define LDSH 40
#define TILE_HALVES (GBM * LDSH)                 // 5120
#define STAGE_HALVES (2 * TILE_HALVES)           // 10240
#define GEMM_SMEM_BYTES (3 * STAGE_HALVES * 2)   // 61440

__global__ void __launch_bounds__(256, 2)
gemm_f16_kernel(const __half* __restrict__ A, const __half* __restrict__ W,
                float* __restrict__ C, int M, int N, int K)
{
    extern __shared__ __half smh[];
    const uint32_t smb = smem_u32(smh);

    const int tid  = threadIdx.x;
    const int wid  = tid >> 5;
    const int lane = tid & 31;
    const int g    = lane >> 2;
    const int t    = lane & 3;
    const int wm0  = (wid >> 2) * 64;
    const int wn0  = (wid & 3) * 32;
    const int m0   = blockIdx.y * GBM;
    const int n0   = blockIdx.x * GBN;

    // ldmatrix per-lane address offsets (bytes, within a stage)
    const uint32_t a_off = 2u * (uint32_t)((wm0 + (lane & 15)) * LDSH + (lane >> 4) * 8);
    const uint32_t b_off = 2u * (uint32_t)((wn0 + (lane & 7)) * LDSH + ((lane >> 3) & 1) * 8);

    const int lrow = tid >> 1;
    const int lch  = (tid & 1) * 16;

    const __half* Ag = A + (size_t)(m0 + lrow) * K + lch;
    const __half* Wg = W + (size_t)(n0 + lrow) * K + lch;

    auto load_stage = [&](int s, int kt) {
        const int k0 = kt * GK;
        const uint32_t sb = smb + (uint32_t)(s * STAGE_HALVES) * 2u;
        const uint32_t off = (uint32_t)(lrow * LDSH + lch) * 2u;
        CP_ASYNC16(sb + off,      Ag + k0);
        CP_ASYNC16(sb + off + 16, Ag + k0 + 8);
        CP_ASYNC16(sb + (uint32_t)TILE_HALVES * 2u + off,      Wg + k0);
        CP_ASYNC16(sb + (uint32_t)TILE_HALVES * 2u + off + 16, Wg + k0 + 8);
        CP_COMMIT();
    };

    float c[4][4][4] = {};

    const int nk = K / GK;
    load_stage(0, 0);
    load_stage(1, 1);

    for (int kt = 0; kt < nk; kt++) {
        if (kt + 1 < nk) { CP_WAIT(1); }
        else             { CP_WAIT(0); }
        __syncthreads();

        if (kt + 2 < nk) load_stage((kt + 2) % 3, kt + 2);

        const uint32_t sa  = smb + (uint32_t)((kt % 3) * STAGE_HALVES) * 2u;
        const uint32_t aad = sa + a_off;
        const uint32_t bad = sa + (uint32_t)TILE_HALVES * 2u + b_off;
        #pragma unroll
        for (int ks = 0; ks < 2; ks++) {
            uint32_t af[4][4], bf[4][2];
            #pragma unroll
            for (int i = 0; i < 4; i++)
                ldsm_x4(af[i], aad + 2u * (uint32_t)(i * 16 * LDSH + ks * 16));
            #pragma unroll
            for (int j = 0; j < 4; j++)
                ldsm_x2(bf[j], bad + 2u * (uint32_t)(j * 8 * LDSH + ks * 16));
            #pragma unroll
            for (int i = 0; i < 4; i++)
                #pragma unroll
                for (int j = 0; j < 4; j++)
                    mma_f16(c[i][j], af[i], bf[j]);
        }
    }

    #pragma unroll
    for (int i = 0; i < 4; i++) {
        #pragma unroll
        for (int j = 0; j < 4; j++) {
            const int row = m0 + wm0 + i * 16 + g;
            const int col = n0 + wn0 + j * 8 + 2 * t;
            *(float2*)(C + (size_t)row * N + col) =
                make_float2(c[i][j][0], c[i][j][1]);
            *(float2*)(C + (size_t)(row + 8) * N + col) =
                make_float2(c[i][j][2], c[i][j][3]);
        }
    }
}

// ===========================================================================
// fp16 flash attention with ldmatrix fragment loads. Causal, GQA.
// qb reversed (heavy CTAs first) for better tail packing.
// ===========================================================================
#define LDKH 72
#define KV_TILE_HALVES (64 * LDKH)                   // 4608
#define ATT_SMEM_BYTES ((6 * KV_TILE_HALVES + 128 * LDKH) * 2)  // 73728

__global__ void __launch_bounds__(256, 2)
attn_f16_kernel(const __half* __restrict__ q, const __half* __restrict__ k,
                const __half* __restrict__ vt, __half* __restrict__ o)
{
    extern __shared__ __half smha[];
    __half* Kst = smha;                           // 3 stages [kv][hd]
    __half* Vst = smha + 3 * KV_TILE_HALVES;      // 3 stages [hd][kv] (V^T)
    __half* Ps  = smha + 6 * KV_TILE_HALVES;      // [128][LDKH]
    const uint32_t Kb32 = smem_u32(Kst);
    const uint32_t Vb32 = smem_u32(Vst);
    const uint32_t Pb32 = smem_u32(Ps);

    const int qb   = (int)gridDim.x - 1 - (int)blockIdx.x;   // heavy first
    const int h    = blockIdx.y;
    const int b    = blockIdx.z;
    const int kvh  = h / REP;
    const int tid  = threadIdx.x;
    const int wid  = tid >> 5;
    const int lane = tid & 31;
    const int g    = lane >> 2;
    const int t    = lane & 3;
    const int R0   = qb * 128 + wid * 16;
    __half* Pw = Ps + (wid * 16) * LDKH;
    const uint32_t Pwb = Pb32 + (uint32_t)(wid * 16 * LDKH) * 2u;

    // ldmatrix per-lane offsets (bytes)
    const uint32_t kb_off = 2u * (uint32_t)(((lane >> 4) * 8 + (lane & 7)) * LDKH
                                            + ((lane >> 3) & 1) * 8);
    const uint32_t p_off = 2u * (uint32_t)((lane & 15) * LDKH + (lane >> 4) * 8);

    const int lr = tid >> 2;
    const int lc = (tid & 3) * 16;
    const __half* kg  = k  + ((size_t)b * SEQ + lr) * KVDIM + kvh * HD + lc;
    const __half* vtg = vt + ((size_t)(b * NKV + kvh) * HD + lr) * SEQ + lc;
    const uint32_t soff = (uint32_t)(lr * LDKH + lc) * 2u;

    auto load_tile = [&](int s, int ti) {
        const uint32_t kd = Kb32 + (uint32_t)(s * KV_TILE_HALVES) * 2u + soff;
        const uint32_t vd = Vb32 + (uint32_t)(s * KV_TILE_HALVES) * 2u + soff;
        const __half* ks = kg + (size_t)ti * 64 * KVDIM;
        const __half* vs = vtg + ti * 64;
        CP_ASYNC16(kd,      ks);
        CP_ASYNC16(kd + 16, ks + 8);
        CP_ASYNC16(vd,      vs);
        CP_ASYNC16(vd + 16, vs + 8);
        CP_COMMIT();
    };

    // ---- Q fragments from gmem ----
    uint32_t aq[4][4];
    {
        const __half* q0 = q + ((size_t)b * SEQ + R0 + g) * DIM + h * HD;
        #pragma unroll
        for (int kf = 0; kf < 4; kf++) {
            const __half* qp = q0 + kf * 16 + 2 * t;
            aq[kf][0] = *(const uint32_t*)(qp);
            aq[kf][1] = *(const uint32_t*)(qp + 8 * DIM);
            aq[kf][2] = *(const uint32_t*)(qp + 8);
            aq[kf][3] = *(const uint32_t*)(qp + 8 * DIM + 8);
        }
    }

    float co[8][4] = {};
    float mr0 = -1e30f, mr1 = -1e30f;
    float lr0 = 0.f, lr1 = 0.f;

    const int ntiles = 2 * qb + 2;
    load_tile(0, 0);
    load_tile(1, 1);

    for (int ti = 0; ti < ntiles; ti++) {
        if (ti + 1 < ntiles) { CP_WAIT(1); }
        else                 { CP_WAIT(0); }
        __syncthreads();

        if (ti + 2 < ntiles) load_tile((ti + 2) % 3, ti + 2);

        if (ti * 64 > R0 + 15) continue;   // warp entirely above diagonal

        const uint32_t Ksb = Kb32 + (uint32_t)((ti % 3) * KV_TILE_HALVES) * 2u + kb_off;
        const uint32_t Vsb = Vb32 + (uint32_t)((ti % 3) * KV_TILE_HALVES) * 2u + kb_off;

        // ---- S = Q K^T ----
        float cs[8][4] = {};
        #pragma unroll
        for (int kf = 0; kf < 4; kf++) {
            #pragma unroll
            for (int m = 0; m < 4; m++) {
                uint32_t r[4];
                ldsm_x4(r, Ksb + 2u * (uint32_t)(m * 16 * LDKH + kf * 16));
                mma_f16(cs[2 * m],     aq[kf], &r[0]);
                mma_f16(cs[2 * m + 1], aq[kf], &r[2]);
            }
        }

        // ---- causal mask (partial tiles only) ----
        const int colbase = ti * 64;
        if (colbase + 63 > R0) {
            const int row0 = R0 + g, row1 = R0 + g + 8;
            #pragma unroll
            for (int nf = 0; nf < 8; nf++) {
                const int c0i = colbase + nf * 8 + 2 * t;
                if (c0i     > row0) cs[nf][0] = -1e9f;
                if (c0i + 1 > row0) cs[nf][1] = -1e9f;
                if (c0i     > row1) cs[nf][2] = -1e9f;
                if (c0i + 1 > row1) cs[nf][3] = -1e9f;
            }
        }

        // ---- online softmax ----
        float mx0 = -1e30f, mx1 = -1e30f;
        #pragma unroll
        for (int nf = 0; nf < 8; nf++) {
            mx0 = fmaxf(mx0, fmaxf(cs[nf][0], cs[nf][1]));
            mx1 = fmaxf(mx1, fmaxf(cs[nf][2], cs[nf][3]));
        }
        mx0 = fmaxf(mx0, __shfl_xor_sync(0xffffffffu, mx0, 1));
        mx0 = fmaxf(mx0, __shfl_xor_sync(0xffffffffu, mx0, 2));
        mx1 = fmaxf(mx1, __shfl_xor_sync(0xffffffffu, mx1, 1));
        mx1 = fmaxf(mx1, __shfl_xor_sync(0xffffffffu, mx1, 2));

        const float mn0 = fmaxf(mr0, mx0);
        const float mn1 = fmaxf(mr1, mx1);
        const float corr0 = __expf(mr0 - mn0);
        const float corr1 = __expf(mr1 - mn1);
        mr0 = mn0; mr1 = mn1;

        float rs0 = 0.f, rs1 = 0.f;
        #pragma unroll
        for (int nf = 0; nf < 8; nf++) {
            cs[nf][0] = __expf(cs[nf][0] - mn0);
            cs[nf][1] = __expf(cs[nf][1] - mn0);
            cs[nf][2] = __expf(cs[nf][2] - mn1);
            cs[nf][3] = __expf(cs[nf][3] - mn1);
            rs0 += cs[nf][0] + cs[nf][1];
            rs1 += cs[nf][2] + cs[nf][3];
        }
        rs0 += __shfl_xor_sync(0xffffffffu, rs0, 1);
        rs0 += __shfl_xor_sync(0xffffffffu, rs0, 2);
        rs1 += __shfl_xor_sync(0xffffffffu, rs1, 1);
        rs1 += __shfl_xor_sync(0xffffffffu, rs1, 2);
        lr0 = lr0 * corr0 + rs0;
        lr1 = lr1 * corr1 + rs1;
        #pragma unroll
        for (int nf = 0; nf < 8; nf++) {
            co[nf][0] *= corr0; co[nf][1] *= corr0;
            co[nf][2] *= corr1; co[nf][3] *= corr1;
        }

        // ---- P -> warp-private smem as half2, then O += P V ----
        #pragma unroll
        for (int nf = 0; nf < 8; nf++) {
            *(__half2*)(Pw + g * LDKH + nf * 8 + 2 * t) =
                __floats2half2_rn(cs[nf][0], cs[nf][1]);
            *(__half2*)(Pw + (g + 8) * LDKH + nf * 8 + 2 * t) =
                __floats2half2_rn(cs[nf][2], cs[nf][3]);
        }
        __syncwarp();

        #pragma unroll
        for (int kf = 0; kf < 4; kf++) {
            uint32_t ap[4];
            ldsm_x4(ap, Pwb + p_off + 2u * (uint32_t)(kf * 16));
            #pragma unroll
            for (int m = 0; m < 4; m++) {
                uint32_t r[4];
                ldsm_x4(r, Vsb + 2u * (uint32_t)(m * 16 * LDKH + kf * 16));
                mma_f16(co[2 * m],     ap, &r[0]);
                mma_f16(co[2 * m + 1], ap, &r[2]);
            }
        }
    }

    // ---- epilogue: fp16 output ----
    const float inv0 = 1.f / lr0;
    const float inv1 = 1.f / lr1;
    __half* o0 = o + ((size_t)b * SEQ + R0 + g) * DIM + h * HD;
    #pragma unroll
    for (int nf = 0; nf < 8; nf++) {
        *(__half2*)(o0 + nf * 8 + 2 * t) =
            __floats2half2_rn(co[nf][0] * inv0, co[nf][1] * inv0);
        *(__half2*)(o0 + 8 * DIM + nf * 8 + 2 * t) =
            __floats2half2_rn(co[nf][2] * inv1, co[nf][3] * inv1);
    }
}

// ---------------------------------------------------------------------------
extern "C" void kernel_launch(void* const* d_in, const int* in_sizes, int n_in,
                              void* d_out, int out_size)
{
    const float* x    = (const float*)d_in[0];
    const float* fcos = (const float*)d_in[1];
    const float* fsin = (const float*)d_in[2];
    const float* wq   = (const float*)d_in[3];
    const float* wk   = (const float*)d_in[4];
    const float* wv   = (const float*)d_in[5];
    const float* wo   = (const float*)d_in[6];
    float* out = (float*)d_out;

    void *qkv_, *xh_, *qh_, *kh_, *vth_, *oh_, *wh_;
    cudaGetSymbolAddress(&qkv_, g_qkv);
    cudaGetSymbolAddress(&xh_, g_xh);
    cudaGetSymbolAddress(&qh_, g_qh);
    cudaGetSymbolAddress(&kh_, g_kh);
    cudaGetSymbolAddress(&vth_, g_vth);
    cudaGetSymbolAddress(&oh_, g_oh);
    cudaGetSymbolAddress(&wh_, g_wh);
    float*  qkv = (float*)qkv_;
    __half* xh  = (__half*)xh_;
    __half* qh  = (__half*)qh_;
    __half* kh  = (__half*)kh_;
    __half* vth = (__half*)vth_;
    __half* oh  = (__half*)oh_;
    __half* wh  = (__half*)wh_;

    const int M = BATCH * SEQ;   // 4096

    cudaFuncSetAttribute(gemm_f16_kernel,
                         cudaFuncAttributeMaxDynamicSharedMemorySize,
                         GEMM_SMEM_BYTES);
    cudaFuncSetAttribute(attn_f16_kernel,
                         cudaFuncAttributeMaxDynamicSharedMemorySize,
                         ATT_SMEM_BYTES);

    // fp32 -> fp16 conversion of x and weights (wq|wk|wv land contiguously)
    {
        int n4;
        n4 = (BATCH * SEQ * DIM) / 4;
        f2h_kernel<<<(n4 + 255) / 256, 256>>>(x, xh, n4);
        n4 = (DIM * DIM) / 4;
        f2h_kernel<<<(n4 + 255) / 256, 256>>>(wq, wh + WQ_OFF, n4);
        n4 = (KVDIM * DIM) / 4;
        f2h_kernel<<<(n4 + 255) / 256, 256>>>(wk, wh + WK_OFF, n4);
        f2h_kernel<<<(n4 + 255) / 256, 256>>>(wv, wh + WV_OFF, n4);
        n4 = (DIM * DIM) / 4;
        f2h_kernel<<<(n4 + 255) / 256, 256>>>(wo, wh + WO_OFF, n4);
    }

    // Fused QKV projection: one GEMM, N = 3072
    gemm_f16_kernel<<<dim3(QKVD / GBN, M / GBM), 256, GEMM_SMEM_BYTES>>>(
        xh, wh, qkv, M, QKVD, DIM);

    // RoPE -> fp16 (q scaled by 1/8) from fused buffer; V transpose+convert
    {
        int tq = BATCH * SEQ * NH * HALFD;
        rope_h_kernel<<<(tq + 255) / 256, 256>>>(qkv, qh, fcos, fsin, NH, 0.125f, 0);
        int tk = BATCH * SEQ * NKV * HALFD;
        rope_h_kernel<<<(tk + 255) / 256, 256>>>(qkv, kh, fcos, fsin, NKV, 1.0f, KCOL);
        vt_kernel<<<dim3(SEQ / 32, HD / 32, BATCH * NKV), dim3(32, 8)>>>(qkv, vth);
    }

    // attention (fp16 mma flash attention, fp16 out)
    attn_f16_kernel<<<dim3(SEQ / 128, NH, BATCH), 256, ATT_SMEM_BYTES>>>(qh, kh, vth, oh);

    // output projection
    gemm_f16_kernel<<<dim3(DIM / GBN, M / GBM), 256, GEMM_SMEM_BYTES>>>(oh, wh + WO_OFF, out, M, DIM, DIM);
}

// round 16
// speedup vs baseline: 2.0146x; 1.0232x over previous
#include <cuda_runtime.h>
#include <cuda_fp16.h>
#include <cstdint>

#define BATCH  2
#define SEQ    2048
#define DIM    2048
#define NH     32
#define NKV    8
#define HD     64
#define KVDIM  (NKV*HD)     // 512
#define REP    (NH/NKV)     // 4
#define HALFD  (HD/2)       // 32
#define QKVD   (DIM + 2*KVDIM)   // 3072 fused projection width
#define KCOL   DIM               // 2048
#define VCOL   (DIM + KVDIM)     // 2560

// ---------------- scratch (device globals; no allocations allowed) ----------
__device__ __align__(16) __half g_xh[(size_t)BATCH*SEQ*DIM];      // fp16 x
__device__ __align__(16) __half g_qh[(size_t)BATCH*SEQ*NH*HD];    // fp16 roped q (scaled)
__device__ __align__(16) __half g_kh[(size_t)BATCH*SEQ*NKV*HD];   // fp16 roped k
__device__ __align__(16) __half g_vh[(size_t)BATCH*SEQ*NKV*HD];   // fp16 v (linear)
__device__ __align__(16) __half g_vth[(size_t)BATCH*NKV*HD*SEQ];  // fp16 V^T
__device__ __align__(16) __half g_oh[(size_t)BATCH*SEQ*NH*HD];    // fp16 attn out
__device__ __align__(16) __half g_wh[(size_t)10485760];           // fp16 weights

#define WQ_OFF 0
#define WK_OFF 4194304
#define WV_OFF 5242880
#define WO_OFF 6291456

__device__ __forceinline__ uint32_t smem_u32(const void* p) {
    uint32_t a;
    asm("{ .reg .u64 t; cvta.to.shared.u64 t, %1; cvt.u32.u64 %0, t; }"
        : "=r"(a) : "l"(p));
    return a;
}

#define CP_ASYNC16(dst, src) \
    asm volatile("cp.async.cg.shared.global [%0], [%1], 16;" \
        :: "r"(dst), "l"(src))
#define CP_COMMIT() asm volatile("cp.async.commit_group;")
#define CP_WAIT(N)  asm volatile("cp.async.wait_group %0;" :: "n"(N))

__device__ __forceinline__ void ldsm_x4(uint32_t r[4], uint32_t addr) {
    asm volatile("ldmatrix.sync.aligned.m8n8.x4.shared.b16 {%0,%1,%2,%3}, [%4];"
        : "=r"(r[0]), "=r"(r[1]), "=r"(r[2]), "=r"(r[3]) : "r"(addr));
}
__device__ __forceinline__ void ldsm_x2(uint32_t r[2], uint32_t addr) {
    asm volatile("ldmatrix.sync.aligned.m8n8.x2.shared.b16 {%0,%1}, [%2];"
        : "=r"(r[0]), "=r"(r[1]) : "r"(addr));
}

// m16n8k16 fp16 mma, fp32 accumulate. A row-major, B col-major (K-major).
__device__ __forceinline__ void mma_f16(float c[4], const uint32_t a[4],
                                        const uint32_t b[2]) {
    asm volatile(
        "mma.sync.aligned.m16n8k16.row.col.f32.f16.f16.f32 "
        "{%0,%1,%2,%3}, {%4,%5,%6,%7}, {%8,%9}, {%0,%1,%2,%3};"
        : "+f"(c[0]), "+f"(c[1]), "+f"(c[2]), "+f"(c[3])
        : "r"(a[0]), "r"(a[1]), "r"(a[2]), "r"(a[3]),
          "r"(b[0]), "r"(b[1]));
}

// ---------------------------------------------------------------------------
// fp32 -> fp16 conversion pass
// ---------------------------------------------------------------------------
__global__ void f2h_kernel(const float* __restrict__ in,
                           __half* __restrict__ out, int n4)
{
    int i = blockIdx.x * blockDim.x + threadIdx.x;
    if (i >= n4) return;
    float4 v = *(const float4*)(in + 4 * (size_t)i);
    __half2* o2 = (__half2*)(out + 4 * (size_t)i);
    o2[0] = __floats2half2_rn(v.x, v.y);
    o2[1] = __floats2half2_rn(v.z, v.w);
}

// ---------------------------------------------------------------------------
// V transpose from linear fp16 vh -> vt [(b*NKV+kv)*HD+d][s]
// ---------------------------------------------------------------------------
__global__ void vt_kernel(const __half* __restrict__ vh, __half* __restrict__ vt)
{
    __shared__ __half tile[32][33];
    const int bx = blockIdx.x;
    const int by = blockIdx.y;
    const int bz = blockIdx.z;
    const int b  = bz / NKV, kv = bz % NKV;
    const int tx = threadIdx.x, ty = threadIdx.y;

    #pragma unroll
    for (int i = 0; i < 4; i++) {
        int s = bx * 32 + ty + i * 8;
        int d = by * 32 + tx;
        tile[ty + i * 8][tx] = vh[(size_t)(b * SEQ + s) * KVDIM + kv * HD + d];
    }
    __syncthreads();
    #pragma unroll
    for (int i = 0; i < 4; i++) {
        int d = by * 32 + ty + i * 8;
        int s = bx * 32 + tx;
        vt[(size_t)(bz * HD + d) * SEQ + s] = tile[tx][ty + i * 8];
    }
}

// ===========================================================================
// fp16 tensor-core GEMM with ldmatrix fragment loads.
// mode 0: write fp32 C.  mode 1: fused qkv epilogue (rope q/k, fp16 out).
// ===========================================================================
#define GBM 128
#define GBN 128
#define GK  32
#define LDSH 40
#define TILE_HALVES (GBM * LDSH)                 // 5120
#define STAGE_HALVES (2 * TILE_HALVES)           // 10240
#define GEMM_SMEM_BYTES (3 * STAGE_HALVES * 2)   // 61440

__global__ void __launch_bounds__(256, 2)
gemm_f16_kernel(const __half* __restrict__ A, const __half* __restrict__ W,
                float* __restrict__ C, int M, int N, int K, int mode,
                __half* __restrict__ qh, __half* __restrict__ kh,
                __half* __restrict__ vh,
                const float* __restrict__ fcos, const float* __restrict__ fsin)
{
    extern __shared__ __half smh[];
    const uint32_t smb = smem_u32(smh);

    const int tid  = threadIdx.x;
    const int wid  = tid >> 5;
    const int lane = tid & 31;
    const int g    = lane >> 2;
    const int t    = lane & 3;
    const int wm0  = (wid >> 2) * 64;
    const int wn0  = (wid & 3) * 32;
    const int m0   = blockIdx.y * GBM;
    const int n0   = blockIdx.x * GBN;

    const uint32_t a_off = 2u * (uint32_t)((wm0 + (lane & 15)) * LDSH + (lane >> 4) * 8);
    const uint32_t b_off = 2u * (uint32_t)((wn0 + (lane & 7)) * LDSH + ((lane >> 3) & 1) * 8);

    const int lrow = tid >> 1;
    const int lch  = (tid & 1) * 16;

    const __half* Ag = A + (size_t)(m0 + lrow) * K + lch;
    const __half* Wg = W + (size_t)(n0 + lrow) * K + lch;

    auto load_stage = [&](int s, int kt) {
        const int k0 = kt * GK;
        const uint32_t sb = smb + (uint32_t)(s * STAGE_HALVES) * 2u;
        const uint32_t off = (uint32_t)(lrow * LDSH + lch) * 2u;
        CP_ASYNC16(sb + off,      Ag + k0);
        CP_ASYNC16(sb + off + 16, Ag + k0 + 8);
        CP_ASYNC16(sb + (uint32_t)TILE_HALVES * 2u + off,      Wg + k0);
        CP_ASYNC16(sb + (uint32_t)TILE_HALVES * 2u + off + 16, Wg + k0 + 8);
        CP_COMMIT();
    };

    float c[4][4][4] = {};

    const int nk = K / GK;
    load_stage(0, 0);
    load_stage(1, 1);

    for (int kt = 0; kt < nk; kt++) {
        if (kt + 1 < nk) { CP_WAIT(1); }
        else             { CP_WAIT(0); }
        __syncthreads();

        if (kt + 2 < nk) load_stage((kt + 2) % 3, kt + 2);

        const uint32_t sa  = smb + (uint32_t)((kt % 3) * STAGE_HALVES) * 2u;
        const uint32_t aad = sa + a_off;
        const uint32_t bad = sa + (uint32_t)TILE_HALVES * 2u + b_off;
        #pragma unroll
        for (int ks = 0; ks < 2; ks++) {
            uint32_t af[4][4], bf[4][2];
            #pragma unroll
            for (int i = 0; i < 4; i++)
                ldsm_x4(af[i], aad + 2u * (uint32_t)(i * 16 * LDSH + ks * 16));
            #pragma unroll
            for (int j = 0; j < 4; j++)
                ldsm_x2(bf[j], bad + 2u * (uint32_t)(j * 8 * LDSH + ks * 16));
            #pragma unroll
            for (int i = 0; i < 4; i++)
                #pragma unroll
                for (int j = 0; j < 4; j++)
                    mma_f16(c[i][j], af[i], bf[j]);
        }
    }

    if (mode == 0) {
        #pragma unroll
        for (int i = 0; i < 4; i++) {
            #pragma unroll
            for (int j = 0; j < 4; j++) {
                const int row = m0 + wm0 + i * 16 + g;
                const int col = n0 + wn0 + j * 8 + 2 * t;
                *(float2*)(C + (size_t)row * N + col) =
                    make_float2(c[i][j][0], c[i][j][1]);
                *(float2*)(C + (size_t)(row + 8) * N + col) =
                    make_float2(c[i][j][2], c[i][j][3]);
            }
        }
        return;
    }

    // ---- fused qkv epilogue; region is uniform per CTA ----
    const int region = (n0 < KCOL) ? 0 : (n0 < VCOL ? 1 : 2);
    #pragma unroll
    for (int i = 0; i < 4; i++) {
        const int row0 = m0 + wm0 + i * 16 + g;
        const int row1 = row0 + 8;
        const int s0 = row0 & (SEQ - 1);
        const int s1 = row1 & (SEQ - 1);
        #pragma unroll
        for (int j = 0; j < 4; j++) {
            const int col = n0 + wn0 + j * 8 + 2 * t;
            const float x00 = c[i][j][0], x01 = c[i][j][1];
            const float x10 = c[i][j][2], x11 = c[i][j][3];
            if (region == 2) {
                const int cc = col - VCOL;
                *(__half2*)(vh + (size_t)row0 * KVDIM + cc) =
                    __floats2half2_rn(x00, x01);
                *(__half2*)(vh + (size_t)row1 * KVDIM + cc) =
                    __floats2half2_rn(x10, x11);
            } else {
                const int p = (col & 63) >> 1;
                const float cv0 = fcos[s0 * HALFD + p], sv0 = fsin[s0 * HALFD + p];
                const float cv1 = fcos[s1 * HALFD + p], sv1 = fsin[s1 * HALFD + p];
                if (region == 0) {
                    *(__half2*)(qh + (size_t)row0 * DIM + col) =
                        __floats2half2_rn((x00 * cv0 - x01 * sv0) * 0.125f,
                                          (x00 * sv0 + x01 * cv0) * 0.125f);
                    *(__half2*)(qh + (size_t)row1 * DIM + col) =
                        __floats2half2_rn((x10 * cv1 - x11 * sv1) * 0.125f,
                                          (x10 * sv1 + x11 * cv1) * 0.125f);
                } else {
                    const int cc = col - KCOL;
                    *(__half2*)(kh + (size_t)row0 * KVDIM + cc) =
                        __floats2half2_rn(x00 * cv0 - x01 * sv0,
                                          x00 * sv0 + x01 * cv0);
                    *(__half2*)(kh + (size_t)row1 * KVDIM + cc) =
                        __floats2half2_rn(x10 * cv1 - x11 * sv1,
                                          x10 * sv1 + x11 * cv1);
                }
            }
        }
    }
}

// ===========================================================================
// fp16 flash attention with ldmatrix fragment loads. Causal, GQA.
// qb reversed (heavy CTAs first) for better tail packing.
// ===========================================================================
#define LDKH 72
#define KV_TILE_HALVES (64 * LDKH)                   // 4608
#define ATT_SMEM_BYTES ((6 * KV_TILE_HALVES + 128 * LDKH) * 2)  // 73728

__global__ void __launch_bounds__(256, 2)
attn_f16_kernel(const __half* __restrict__ q, const __half* __restrict__ k,
                const __half* __restrict__ vt, __half* __restrict__ o)
{
    extern __shared__ __half smha[];
    __half* Kst = smha;
    __half* Vst = smha + 3 * KV_TILE_HALVES;
    __half* Ps  = smha + 6 * KV_TILE_HALVES;
    const uint32_t Kb32 = smem_u32(Kst);
    const uint32_t Vb32 = smem_u32(Vst);
    const uint32_t Pb32 = smem_u32(Ps);

    const int qb   = (int)gridDim.x - 1 - (int)blockIdx.x;
    const int h    = blockIdx.y;
    const int b    = blockIdx.z;
    const int kvh  = h / REP;
    const int tid  = threadIdx.x;
    const int wid  = tid >> 5;
    const int lane = tid & 31;
    const int g    = lane >> 2;
    const int t    = lane & 3;
    const int R0   = qb * 128 + wid * 16;
    __half* Pw = Ps + (wid * 16) * LDKH;
    const uint32_t Pwb = Pb32 + (uint32_t)(wid * 16 * LDKH) * 2u;

    const uint32_t kb_off = 2u * (uint32_t)(((lane >> 4) * 8 + (lane & 7)) * LDKH
                                            + ((lane >> 3) & 1) * 8);
    const uint32_t p_off = 2u * (uint32_t)((lane & 15) * LDKH + (lane >> 4) * 8);

    const int lr = tid >> 2;
    const int lc = (tid & 3) * 16;
    const __half* kg  = k  + ((size_t)b * SEQ + lr) * KVDIM + kvh * HD + lc;
    const __half* vtg = vt + ((size_t)(b * NKV + kvh) * HD + lr) * SEQ + lc;
    const uint32_t soff = (uint32_t)(lr * LDKH + lc) * 2u;

    auto load_tile = [&](int s, int ti) {
        const uint32_t kd = Kb32 + (uint32_t)(s * KV_TILE_HALVES) * 2u + soff;
        const uint32_t vd = Vb32 + (uint32_t)(s * KV_TILE_HALVES) * 2u + soff;
        const __half* ks = kg + (size_t)ti * 64 * KVDIM;
        const __half* vs = vtg + ti * 64;
        CP_ASYNC16(kd,      ks);
        CP_ASYNC16(kd + 16, ks + 8);
        CP_ASYNC16(vd,      vs);
        CP_ASYNC16(vd + 16, vs + 8);
        CP_COMMIT();
    };

    uint32_t aq[4][4];
    {
        const __half* q0 = q + ((size_t)b * SEQ + R0 + g) * DIM + h * HD;
        #pragma unroll
        for (int kf = 0; kf < 4; kf++) {
            const __half* qp = q0 + kf * 16 + 2 * t;
            aq[kf][0] = *(const uint32_t*)(qp);
            aq[kf][1] = *(const uint32_t*)(qp + 8 * DIM);
            aq[kf][2] = *(const uint32_t*)(qp + 8);
            aq[kf][3] = *(const uint32_t*)(qp + 8 * DIM + 8);
        }
    }

    float co[8][4] = {};
    float mr0 = -1e30f, mr1 = -1e30f;
    float lr0 = 0.f, lr1 = 0.f;

    const int ntiles = 2 * qb + 2;
    load_tile(0, 0);
    load_tile(1, 1);

    for (int ti = 0; ti < ntiles; ti++) {
        if (ti + 1 < ntiles) { CP_WAIT(1); }
        else                 { CP_WAIT(0); }
        __syncthreads();

        if (ti + 2 < ntiles) load_tile((ti + 2) % 3, ti + 2);

        if (ti * 64 > R0 + 15) continue;

        const uint32_t Ksb = Kb32 + (uint32_t)((ti % 3) * KV_TILE_HALVES) * 2u + kb_off;
        const uint32_t Vsb = Vb32 + (uint32_t)((ti % 3) * KV_TILE_HALVES) * 2u + kb_off;

        float cs[8][4] = {};
        #pragma unroll
        for (int kf = 0; kf < 4; kf++) {
            #pragma unroll
            for (int m = 0; m < 4; m++) {
                uint32_t r[4];
                ldsm_x4(r, Ksb + 2u * (uint32_t)(m * 16 * LDKH + kf * 16));
                mma_f16(cs[2 * m],     aq[kf], &r[0]);
                mma_f16(cs[2 * m + 1], aq[kf], &r[2]);
            }
        }

        const int colbase = ti * 64;
        if (colbase + 63 > R0) {
            const int row0 = R0 + g, row1 = R0 + g + 8;
            #pragma unroll
            for (int nf = 0; nf < 8; nf++) {
                const int c0i = colbase + nf * 8 + 2 * t;
                if (c0i     > row0) cs[nf][0] = -1e9f;
                if (c0i + 1 > row0) cs[nf][1] = -1e9f;
                if (c0i     > row1) cs[nf][2] = -1e9f;
                if (c0i + 1 > row1) cs[nf][3] = -1e9f;
            }
        }

        float mx0 = -1e30f, mx1 = -1e30f;
        #pragma unroll
        for (int nf = 0; nf < 8; nf++) {
            mx0 = fmaxf(mx0, fmaxf(cs[nf][0], cs[nf][1]));
            mx1 = fmaxf(mx1, fmaxf(cs[nf][2], cs[nf][3]));
        }
        mx0 = fmaxf(mx0, __shfl_xor_sync(0xffffffffu, mx0, 1));
        mx0 = fmaxf(mx0, __shfl_xor_sync(0xffffffffu, mx0, 2));
        mx1 = fmaxf(mx1, __shfl_xor_sync(0xffffffffu, mx1, 1));
        mx1 = fmaxf(mx1, __shfl_xor_sync(0xffffffffu, mx1, 2));

        const float mn0 = fmaxf(mr0, mx0);
        const float mn1 = fmaxf(mr1, mx1);
        const float corr0 = __expf(mr0 - mn0);
        const float corr1 = __expf(mr1 - mn1);
        mr0 = mn0; mr1 = mn1;

        float rs0 = 0.f, rs1 = 0.f;
        #pragma unroll
        for (int nf = 0; nf < 8; nf++) {
            cs[nf][0] = __expf(cs[nf][0] - mn0);
            cs[nf][1] = __expf(cs[nf][1] - mn0);
            cs[nf][2] = __expf(cs[nf][2] - mn1);
            cs[nf][3] = __expf(cs[nf][3] - mn1);
            rs0 += cs[nf][0] + cs[nf][1];
            rs1 += cs[nf][2] + cs[nf][3];
        }
        rs0 += __shfl_xor_sync(0xffffffffu, rs0, 1);
        rs0 += __shfl_xor_sync(0xffffffffu, rs0, 2);
        rs1 += __shfl_xor_sync(0xffffffffu, rs1, 1);
        rs1 += __shfl_xor_sync(0xffffffffu, rs1, 2);
        lr0 = lr0 * corr0 + rs0;
        lr1 = lr1 * corr1 + rs1;
        #pragma unroll
        for (int nf = 0; nf < 8; nf++) {
            co[nf][0] *= corr0; co[nf][1] *= corr0;
            co[nf][2] *= corr1; co[nf][3] *= corr1;
        }

        #pragma unroll
        for (int nf = 0; nf < 8; nf++) {
            *(__half2*)(Pw + g * LDKH + nf * 8 + 2 * t) =
                __floats2half2_rn(cs[nf][0], cs[nf][1]);
            *(__half2*)(Pw + (g + 8) * LDKH + nf * 8 + 2 * t) =
                __floats2half2_rn(cs[nf][2], cs[nf][3]);
        }
        __syncwarp();

        #pragma unroll
        for (int kf = 0; kf < 4; kf++) {
            uint32_t ap[4];
            ldsm_x4(ap, Pwb + p_off + 2u * (uint32_t)(kf * 16));
            #pragma unroll
            for (int m = 0; m < 4; m++) {
                uint32_t r[4];
                ldsm_x4(r, Vsb + 2u * (uint32_t)(m * 16 * LDKH + kf * 16));
                mma_f16(co[2 * m],     ap, &r[0]);
                mma_f16(co[2 * m + 1], ap, &r[2]);
            }
        }
    }

    const float inv0 = 1.f / lr0;
    const float inv1 = 1.f / lr1;
    __half* o0 = o + ((size_t)b * SEQ + R0 + g) * DIM + h * HD;
    #pragma unroll
    for (int nf = 0; nf < 8; nf++) {
        *(__half2*)(o0 + nf * 8 + 2 * t) =
            __floats2half2_rn(co[nf][0] * inv0, co[nf][1] * inv0);
        *(__half2*)(o0 + 8 * DIM + nf * 8 + 2 * t) =
            __floats2half2_rn(co[nf][2] * inv1, co[nf][3] * inv1);
    }
}

// ---------------------------------------------------------------------------
extern "C" void kernel_launch(void* const* d_in, const int* in_sizes, int n_in,
                              void* d_out, int out_size)
{
    const float* x    = (const float*)d_in[0];
    const float* fcos = (const float*)d_in[1];
    const float* fsin = (const float*)d_in[2];
    const float* wq   = (const float*)d_in[3];
    const float* wk   = (const float*)d_in[4];
    const float* wv   = (const float*)d_in[5];
    const float* wo   = (const float*)d_in[6];
    float* out = (float*)d_out;

    void *xh_, *qh_, *kh_, *vh_, *vth_, *oh_, *wh_;
    cudaGetSymbolAddress(&xh_, g_xh);
    cudaGetSymbolAddress(&qh_, g_qh);
    cudaGetSymbolAddress(&kh_, g_kh);
    cudaGetSymbolAddress(&vh_, g_vh);
    cudaGetSymbolAddress(&vth_, g_vth);
    cudaGetSymbolAddress(&oh_, g_oh);
    cudaGetSymbolAddress(&wh_, g_wh);
    __half* xh  = (__half*)xh_;
    __half* qh  = (__half*)qh_;
    __half* kh  = (__half*)kh_;
    __half* vh  = (__half*)vh_;
    __half* vth = (__half*)vth_;
    __half* oh  = (__half*)oh_;
    __half* wh  = (__half*)wh_;

    const int M = BATCH * SEQ;   // 4096

    cudaFuncSetAttribute(gemm_f16_kernel,
                         cudaFuncAttributeMaxDynamicSharedMemorySize,
                         GEMM_SMEM_BYTES);
    cudaFuncSetAttribute(attn_f16_kernel,
                         cudaFuncAttributeMaxDynamicSharedMemorySize,
                         ATT_SMEM_BYTES);

    // fp32 -> fp16 conversion of x and weights (wq|wk|wv land contiguously)
    {
        int n4;
        n4 = (BATCH * SEQ * DIM) / 4;
        f2h_kernel<<<(n4 + 255) / 256, 256>>>(x, xh, n4);
        n4 = (DIM * DIM) / 4;
        f2h_kernel<<<(n4 + 255) / 256, 256>>>(wq, wh + WQ_OFF, n4);
        n4 = (KVDIM * DIM) / 4;
        f2h_kernel<<<(n4 + 255) / 256, 256>>>(wk, wh + WK_OFF, n4);
        f2h_kernel<<<(n4 + 255) / 256, 256>>>(wv, wh + WV_OFF, n4);
        n4 = (DIM * DIM) / 4;
        f2h_kernel<<<(n4 + 255) / 256, 256>>>(wo, wh + WO_OFF, n4);
    }

    // Fused QKV projection with RoPE+fp16 epilogue (mode 1)
    gemm_f16_kernel<<<dim3(QKVD / GBN, M / GBM), 256, GEMM_SMEM_BYTES>>>(
        xh, wh, nullptr, M, QKVD, DIM, 1, qh, kh, vh, fcos, fsin);

    // V transpose (fp16 -> fp16)
    vt_kernel<<<dim3(SEQ / 32, HD / 32, BATCH * NKV), dim3(32, 8)>>>(vh, vth);

    // attention (fp16 mma flash attention, fp16 out)
    attn_f16_kernel<<<dim3(SEQ / 128, NH, BATCH), 256, ATT_SMEM_BYTES>>>(qh, kh, vth, oh);

    // output projection (mode 0: fp32 out)
    gemm_f16_kernel<<<dim3(DIM / GBN, M / GBM), 256, GEMM_SMEM_BYTES>>>(
        oh, wh + WO_OFF, out, M, DIM, DIM, 0,
        nullptr, nullptr, nullptr, nullptr, nullptr);
}